// round 12
// baseline (speedup 1.0000x reference)
#include <cuda_runtime.h>
#include <math.h>
#include <stdint.h>

#define SC   0.94868329805051381f
#define SCD  0.94868329805051380976
#define MAXND (0.996/0.94868329805051380976)

// fp32 constants exactly as jnp-traced fp32 sees them
#define SCF   ((float)0.94868329805051380976)        // fl32(SQRT_C)
#define MAXNF ((float)(0.996/0.94868329805051380976))// fl32(maxnorm)
#define CLIPF ((float)(1.0 - 1e-7))
#define T2F   ((float)(2.0/0.94868329805051380976))  // fl32(2/SQRT_C)

// ---------------- scratch (device globals; no allocs allowed) ----------------
__device__ float  g_smax[4*768];
__device__ float  g_cmax[4*20*768];
__device__ float  g_embs[4*22*512];     // j: 0=doc, 1=summary, 2..21=cands
__device__ double g_embn2d[4*22];
__device__ float  g_gram[4*1019*512];
__device__ float  g_dweraw[4*1019*512];
__device__ float  g_S[4*1024*22];       // 1/pdist (inverse distances)
__device__ float  g_sspd[4];            // emulated -pdist(summary,doc)^2
__device__ float  g_emud[4*512];        // raw doc GEMM rows (pre-expmap0)
__device__ float  g_emus[4*512];        // raw summary GEMM rows (pre-expmap0)

// ---------------- closed-form pdist (DOUBLE: direct pairs only) --------------
__device__ __forceinline__ double pdist_z(double x2, double y2, double xy) {
    double A   = 1.0 - 1.8*xy + 0.9*y2;
    double B   = 1.0 - 0.9*x2;
    double den = 1.0 - 1.8*xy + 0.81*x2*y2;
    den = fmax(den, 1e-15);
    double num2 = A*A*x2 - 2.0*A*B*xy + B*B*y2;
    double nd2  = num2/(den*den);
    double n    = sqrt(fmax(nd2, 1e-30));
    return fmin(SCD*n, 1.0 - 1e-7);
}
__device__ __forceinline__ double pdist_d(double x2, double y2, double xy) {
    return (2.0/SCD)*atanh(pdist_z(x2, y2, xy));
}
// word-pair pdist: pure fp32 (feeds only cos ratios; noise averages out)
__device__ __forceinline__ float pdist_wf(float x2, float y2, float xy) {
    float A   = 1.f - 1.8f*xy + 0.9f*y2;
    float B   = 1.f - 0.9f*x2;
    float den = fmaxf(1.f - 1.8f*xy + 0.81f*x2*y2, 1e-15f);
    float num2 = A*A*x2 - 2.f*A*B*xy + B*B*y2;
    float nd2  = num2/(den*den);
    float n    = sqrtf(fmaxf(nd2, 1e-30f));
    float z    = fminf(SC*n, 1.f - 1e-7f);
    return (2.f/SC)*atanhf(z);
}

// ---------------- max over sequence dims ----------------
__global__ void maxk(const float* __restrict__ sum_out,
                     const float* __restrict__ cand_out) {
    int idx = blockIdx.x*blockDim.x + threadIdx.x;
    if (idx < 3072) {
        int b = idx/768, h = idx - b*768;
        const float* p = sum_out + (long)b*128*768 + h;
        float m = -3.4e38f;
        for (int l = 0; l < 128; l++) m = fmaxf(m, p[(long)l*768]);
        g_smax[idx] = m;
    } else {
        int i = idx - 3072;
        if (i < 61440) {
            int bc = i/768, h = i - bc*768;
            const float* p = cand_out + (long)bc*128*768 + h;
            float m = -3.4e38f;
            for (int l = 0; l < 128; l++) m = fmaxf(m, p[(long)l*768]);
            g_cmax[i] = m;
        }
    }
}

// ====== small GEMMs as per-row chain kernels (bit-identical fmaf chains) =====
__global__ __launch_bounds__(128) void rowgemm(
    const float* __restrict__ text, const float* __restrict__ Wd,
    const float* __restrict__ Ws,   const float* __restrict__ Wc)
{
    int r = blockIdx.x, t = threadIdx.x;
    const float* A; const float* B; float* C; float* C2 = nullptr;
    if (r < 80) {
        A = g_cmax + r*768; B = Wc;
        C = g_embs + ((long)(r/20)*22 + 2 + (r%20))*512;
    } else if (r < 84) {
        int b = r - 80;
        A = text + (long)b*512*768; B = Wd;
        C = g_embs + (long)(b*22)*512; C2 = g_emud + b*512;
    } else {
        int b = r - 84;
        A = g_smax + b*768; B = Ws;
        C = g_embs + (long)(b*22 + 1)*512; C2 = g_emus + b*512;
    }
    __shared__ float sa[768];
    for (int i = t; i < 768; i += 128) sa[i] = A[i];
    __syncthreads();
    int c = t*4;
    float a0 = 0.f, a1 = 0.f, a2 = 0.f, a3 = 0.f;
    for (int k = 0; k < 768; k++) {
        float4 bv = *(const float4*)(B + (long)k*512 + c);
        float ak = sa[k];
        a0 = __fmaf_rn(ak, bv.x, a0);
        a1 = __fmaf_rn(ak, bv.y, a1);
        a2 = __fmaf_rn(ak, bv.z, a2);
        a3 = __fmaf_rn(ak, bv.w, a3);
    }
    C[c]   = a0 + 0.f; C[c+1] = a1 + 0.f; C[c+2] = a2 + 0.f; C[c+3] = a3 + 0.f;
    if (C2) { C2[c] = a0; C2[c+1] = a1; C2[c+2] = a2; C2[c+3] = a3; }
}

// ================= tf32 tensor-core GEMM v2: BM=128 BN=128 BK=16 =============
struct GP {
    const float* A; const float* B; const float* bias; float* C;
    int M, K, RPB; long IB, IL, IO; int OB, OO, relu;
};
struct TP3 { GP g[3]; int end[3]; };

__device__ __forceinline__ float to_tf32(float x) {
    uint32_t r;
    asm("cvt.rna.tf32.f32 %0, %1;" : "=r"(r) : "f"(x));
    return __uint_as_float(r);
}

#define APAD 20
__global__ __launch_bounds__(256) void gemmT(TP3 ps) {
    __shared__ float As[2][128][APAD];   // [m][k], tf32-rounded
    __shared__ float Bs[2][128][APAD];   // [n][k], tf32-rounded
    int id = blockIdx.x;
    int pi = 0, base = 0;
#pragma unroll
    for (int q = 0; q < 3; q++) {
        if (id >= ps.end[q]) { pi = q + 1; base = ps.end[q]; }
    }
    GP p = ps.g[pi];
    int bx = id - base;
    int bm = (bx >> 2) * 128, bn = (bx & 3) * 128;
    int t = threadIdx.x;
    int w = t >> 5, lane = t & 31;
    int g = lane >> 2, tig = lane & 3;
    int wm = w & 1, wn = w >> 1;          // 2 m-warps x 4 n-warps

    // ---- A staging: idx=t and t+256 -> row idx>>2, k-quad (idx&3)*4
    int r0i = t >> 2, r1i = (t + 256) >> 2;
    int kq0 = (t & 3) * 4;
    int gr0 = bm + r0i; if (gr0 >= p.M) gr0 = p.M - 1;
    int gr1 = bm + r1i; if (gr1 >= p.M) gr1 = p.M - 1;
    int ab0 = gr0 / p.RPB, al0 = gr0 - ab0 * p.RPB;
    int ab1 = gr1 / p.RPB, al1 = gr1 - ab1 * p.RPB;
    const float* Ap0 = p.A + ab0 * p.IB + (long)al0 * p.IL + p.IO + kq0;
    const float* Ap1 = p.A + ab1 * p.IB + (long)al1 * p.IL + p.IO + kq0;
    // ---- B staging: n = t&127, k-range (t>>7)*8 .. +7, scalar k-strided loads
    int sn  = t & 127;
    int kup = (t >> 7) * 8;
    const float* Bq = p.B + (long)kup * 512 + bn + sn;

    float acc[4][4][4];
#pragma unroll
    for (int i = 0; i < 4; i++)
#pragma unroll
        for (int j = 0; j < 4; j++)
#pragma unroll
            for (int r = 0; r < 4; r++) acc[i][j][r] = 0.f;

    int ntiles = p.K >> 4;
    float4 pa0 = *(const float4*)(Ap0);
    float4 pa1 = *(const float4*)(Ap1);
    float pb[8];
#pragma unroll
    for (int i = 0; i < 8; i++) pb[i] = Bq[(long)i * 512];
    {
        float4 ca0 = { to_tf32(pa0.x), to_tf32(pa0.y), to_tf32(pa0.z), to_tf32(pa0.w) };
        float4 ca1 = { to_tf32(pa1.x), to_tf32(pa1.y), to_tf32(pa1.z), to_tf32(pa1.w) };
        *(float4*)&As[0][r0i][kq0] = ca0;
        *(float4*)&As[0][r1i][kq0] = ca1;
        float4 cb0 = { to_tf32(pb[0]), to_tf32(pb[1]), to_tf32(pb[2]), to_tf32(pb[3]) };
        float4 cb1 = { to_tf32(pb[4]), to_tf32(pb[5]), to_tf32(pb[6]), to_tf32(pb[7]) };
        *(float4*)&Bs[0][sn][kup]     = cb0;
        *(float4*)&Bs[0][sn][kup + 4] = cb1;
    }
    __syncthreads();

    for (int tile = 0; tile < ntiles; tile++) {
        int buf = tile & 1;
        if (tile + 1 < ntiles) {
            long ko = (long)(tile + 1) * 16;
            pa0 = *(const float4*)(Ap0 + ko);
            pa1 = *(const float4*)(Ap1 + ko);
#pragma unroll
            for (int i = 0; i < 8; i++) pb[i] = Bq[ko * 512 + (long)i * 512];
        }
#pragma unroll
        for (int ks = 0; ks < 16; ks += 8) {
            uint32_t af[4][4];
#pragma unroll
            for (int mi = 0; mi < 4; mi++) {
                int r = wm*64 + mi*16 + g;
                af[mi][0] = __float_as_uint(As[buf][r    ][ks + tig]);
                af[mi][1] = __float_as_uint(As[buf][r + 8][ks + tig]);
                af[mi][2] = __float_as_uint(As[buf][r    ][ks + tig + 4]);
                af[mi][3] = __float_as_uint(As[buf][r + 8][ks + tig + 4]);
            }
            uint32_t bfr[4][2];
#pragma unroll
            for (int ni = 0; ni < 4; ni++) {
                int n = wn*32 + ni*8 + g;
                bfr[ni][0] = __float_as_uint(Bs[buf][n][ks + tig]);
                bfr[ni][1] = __float_as_uint(Bs[buf][n][ks + tig + 4]);
            }
#pragma unroll
            for (int mi = 0; mi < 4; mi++)
#pragma unroll
                for (int ni = 0; ni < 4; ni++) {
                    asm volatile(
                        "mma.sync.aligned.m16n8k8.row.col.f32.tf32.tf32.f32 "
                        "{%0,%1,%2,%3}, {%4,%5,%6,%7}, {%8,%9}, {%0,%1,%2,%3};"
                        : "+f"(acc[mi][ni][0]), "+f"(acc[mi][ni][1]),
                          "+f"(acc[mi][ni][2]), "+f"(acc[mi][ni][3])
                        : "r"(af[mi][0]), "r"(af[mi][1]), "r"(af[mi][2]), "r"(af[mi][3]),
                          "r"(bfr[ni][0]), "r"(bfr[ni][1]));
                }
        }
        if (tile + 1 < ntiles) {
            int nb = buf ^ 1;
            float4 ca0 = { to_tf32(pa0.x), to_tf32(pa0.y), to_tf32(pa0.z), to_tf32(pa0.w) };
            float4 ca1 = { to_tf32(pa1.x), to_tf32(pa1.y), to_tf32(pa1.z), to_tf32(pa1.w) };
            *(float4*)&As[nb][r0i][kq0] = ca0;
            *(float4*)&As[nb][r1i][kq0] = ca1;
            float4 cb0 = { to_tf32(pb[0]), to_tf32(pb[1]), to_tf32(pb[2]), to_tf32(pb[3]) };
            float4 cb1 = { to_tf32(pb[4]), to_tf32(pb[5]), to_tf32(pb[6]), to_tf32(pb[7]) };
            *(float4*)&Bs[nb][sn][kup]     = cb0;
            *(float4*)&Bs[nb][sn][kup + 4] = cb1;
            __syncthreads();
        }
    }

    // epilogue: c regs {0,1}=row g, {2,3}=row g+8; cols 2*tig, 2*tig+1
#pragma unroll
    for (int mi = 0; mi < 4; mi++) {
#pragma unroll
        for (int half = 0; half < 2; half++) {
            int gm = bm + wm*64 + mi*16 + g + half*8;
            if (gm < p.M) {
                int ob = gm / p.RPB, ol = gm - ob*p.RPB;
                float* Crow = p.C + ((long)ob*p.OB + p.OO + ol)*512;
#pragma unroll
                for (int ni = 0; ni < 4; ni++) {
                    int col = bn + wn*32 + ni*8 + 2*tig;
                    float b0 = p.bias ? p.bias[col]   : 0.f;
                    float b1 = p.bias ? p.bias[col+1] : 0.f;
                    float v0 = acc[mi][ni][half*2+0] + b0;
                    float v1 = acc[mi][ni][half*2+1] + b1;
                    if (p.relu) { v0 = fmaxf(v0, 0.f); v1 = fmaxf(v1, 0.f); }
                    Crow[col]   = v0;
                    Crow[col+1] = v1;
                }
            }
        }
    }
}

// ---------------- expmap0 on the 88 small embedding rows (in place, double) --
__global__ __launch_bounds__(128) void epi_small() {
    int row = blockIdx.x;
    float* u = g_embs + (long)row*512;
    int t = threadIdx.x;
    float4 v = ((float4*)u)[t];
    double s = (double)v.x*v.x + (double)v.y*v.y + (double)v.z*v.z + (double)v.w*v.w;
    for (int o = 16; o; o >>= 1) s += __shfl_xor_sync(~0u, s, o);
    __shared__ double sw[4];
    if ((t & 31) == 0) sw[t >> 5] = s;
    __syncthreads();
    s = sw[0] + sw[1] + sw[2] + sw[3];
    double n = sqrt(fmax(s, 1e-30));
    double scn = SCD*n;
    double tt = tanh(scn);
    double f = tt/scn;
    double gn = tt/SCD;
    if (gn > MAXND) f *= MAXND/gn;
    float ff = (float)f;
    v.x *= ff; v.y *= ff; v.z *= ff; v.w *= ff;
    ((float4*)u)[t] = v;
    if (t == 0) { double xn = fmin(gn, MAXND); g_embn2d[row] = xn*xn; }
}

// =============== bit-replication of the reference summary-doc pdist ==========
__device__ __forceinline__ float xla_red_sq(const float* v, int lane) {
    float a = 0.f;
    for (int m = 0; m < 16; m++) a = __fadd_rn(a, __fmul_rn(v[lane + 32*m], v[lane + 32*m]));
    for (int off = 16; off; off >>= 1) a = __fadd_rn(a, __shfl_down_sync(0xffffffffu, a, off));
    return __shfl_sync(0xffffffffu, a, 0);
}
__device__ __forceinline__ float xla_red_dotneg(const float* v1, const float* v2, int lane) {
    float a = 0.f;
    for (int m = 0; m < 16; m++) {
        int i = lane + 32*m;
        a = __fadd_rn(a, __fmul_rn(-v1[i], v2[i]));
    }
    for (int off = 16; off; off >>= 1) a = __fadd_rn(a, __shfl_down_sync(0xffffffffu, a, off));
    return __shfl_sync(0xffffffffu, a, 0);
}

__global__ __launch_bounds__(512) void emu_rest() {
    int b = blockIdx.x, t = threadIdx.x;
    __shared__ float ud[512], us[512], gd[512], gs[512], xd[512], xs[512], dv[512];
    __shared__ float sc[10];
    ud[t] = g_emud[b*512 + t];
    us[t] = g_emus[b*512 + t];
    __syncthreads();
    if (t < 32) {
        float n2 = xla_red_sq(ud, t);
        float nu = fmaxf(__fsqrt_rn(fmaxf(n2, 1e-30f)), 1e-15f);
        float scn = __fmul_rn(SCF, nu);
        if (t == 0) { sc[0] = scn; sc[2] = (float)tanh((double)scn); }
        n2 = xla_red_sq(us, t);
        nu = fmaxf(__fsqrt_rn(fmaxf(n2, 1e-30f)), 1e-15f);
        scn = __fmul_rn(SCF, nu);
        if (t == 0) { sc[1] = scn; sc[3] = (float)tanh((double)scn); }
    }
    __syncthreads();
    gd[t] = __fdiv_rn(__fmul_rn(sc[2], ud[t]), sc[0]);
    gs[t] = __fdiv_rn(__fmul_rn(sc[3], us[t]), sc[1]);
    __syncthreads();
    if (t < 32) {
        float n2 = xla_red_sq(gd, t);
        float ng = fmaxf(__fsqrt_rn(fmaxf(n2, 1e-30f)), 1e-15f);
        if (t == 0) sc[4] = ng;
        n2 = xla_red_sq(gs, t);
        ng = fmaxf(__fsqrt_rn(fmaxf(n2, 1e-30f)), 1e-15f);
        if (t == 0) sc[5] = ng;
    }
    __syncthreads();
    xd[t] = (sc[4] > MAXNF) ? __fmul_rn(__fdiv_rn(gd[t], sc[4]), MAXNF) : gd[t];
    xs[t] = (sc[5] > MAXNF) ? __fmul_rn(__fdiv_rn(gs[t], sc[5]), MAXNF) : gs[t];
    __syncthreads();
    if (t < 32) {
        float x2 = xla_red_sq(xs, t);
        float y2 = xla_red_sq(xd, t);
        float xy = xla_red_dotneg(xs, xd, t);
        if (t == 0) {
            float t18  = __fmul_rn(1.8f, xy);
            float base = __fadd_rn(1.0f, t18);
            sc[6] = __fadd_rn(base, __fmul_rn(0.9f, y2));
            sc[7] = __fsub_rn(1.0f, __fmul_rn(0.9f, x2));
            float den = __fadd_rn(base, __fmul_rn(__fmul_rn(0.81f, x2), y2));
            sc[8] = fmaxf(den, 1e-15f);
        }
    }
    __syncthreads();
    {
        float xm  = -xs[t];
        float num = __fadd_rn(__fmul_rn(sc[6], xm), __fmul_rn(sc[7], xd[t]));
        dv[t] = __fdiv_rn(num, sc[8]);
    }
    __syncthreads();
    if (t < 32) {
        float n2 = xla_red_sq(dv, t);
        if (t == 0) {
            float nn = __fsqrt_rn(fmaxf(n2, 1e-30f));
            float z  = __fmul_rn(SCF, nn);
            z = fminf(z, CLIPF); z = fmaxf(z, -CLIPF);
            float at = (float)atanh((double)z);
            float pd = __fmul_rn(T2F, at);
            g_sspd[b] = -__fmul_rn(pd, pd);
        }
    }
}

// ------- fused expmap0(norm) + 22 dots + fp32 inverse pdist per word row -----
__global__ __launch_bounds__(256) void rowops() {
    int b = blockIdx.x;
    int l0 = blockIdx.y * 16;
    __shared__ float  se[22*512];
    __shared__ float  sdots[16][22];
    __shared__ float  sf[16];
    __shared__ float  sx2[16];
    __shared__ float  sy2[22];
    int t = threadIdx.x;
    for (int i = t; i < 11264; i += 256) se[i] = g_embs[(long)b*11264 + i];
    if (t < 22) sy2[t] = (float)g_embn2d[b*22 + t];
    __syncthreads();
    int r = t >> 4, cg = t & 15;
    int l = l0 + r;
    int lv = (l < 1019) ? l : 1018;
    const float* u = g_dweraw + ((long)b*1019 + lv)*512;
    float4 ur[8];
#pragma unroll
    for (int i = 0; i < 8; i++) ur[i] = ((const float4*)u)[cg + i*16];
    float s = 0.f;
#pragma unroll
    for (int i = 0; i < 8; i++)
        s += ur[i].x*ur[i].x + ur[i].y*ur[i].y + ur[i].z*ur[i].z + ur[i].w*ur[i].w;
    for (int o = 8; o; o >>= 1) s += __shfl_xor_sync(~0u, s, o);
    {
        float n = sqrtf(fmaxf(s, 1e-30f));
        float scn = SC*n, tt = tanhf(scn);
        float f = tt/scn, gn = tt/SC;
        if (gn > MAXNF) f *= MAXNF/gn;
        if (cg == 0) {
            sf[r] = f;
            float xn = fminf(gn, MAXNF);
            sx2[r] = xn*xn;
        }
    }
    for (int j = 0; j < 22; j++) {
        const float4* e = (const float4*)(se + j*512);
        float d = 0.f;
#pragma unroll
        for (int i = 0; i < 8; i++) {
            float4 ev = e[cg + i*16];
            d += ur[i].x*ev.x + ur[i].y*ev.y + ur[i].z*ev.z + ur[i].w*ev.w;
        }
        for (int o = 8; o; o >>= 1) d += __shfl_xor_sync(~0u, d, o);
        if (cg == 0) sdots[r][j] = d;
    }
    __syncthreads();
    for (int item = t; item < 352; item += 256) {
        int r2 = item/22, j = item - r2*22;
        int l2 = l0 + r2;
        if (l2 < 1019) {
            float xy = sf[r2] * sdots[r2][j];
            float pd = pdist_wf(sx2[r2], sy2[j], xy);
            g_S[((long)b*1024 + l2)*22 + j] = 1.f/pd;
        }
    }
}

// ---------------- final scoring ----------------
__global__ __launch_bounds__(256) void finalk(float* __restrict__ out) {
    int b = blockIdx.x, t = threadIdx.x;
    int w = t >> 5, lane = t & 31;
    __shared__ double sd[22];
    const float4* e0 = (const float4*)(g_embs + (long)b*11264);
    for (int j = w; j < 22; j += 8) {
        const float4* ej = (const float4*)(g_embs + (long)b*11264 + j*512);
        double d = 0.0;
        for (int i = lane; i < 128; i += 32) {
            float4 a = e0[i], c = ej[i];
            d += (double)a.x*c.x + (double)a.y*c.y + (double)a.z*c.z + (double)a.w*c.w;
        }
        for (int o = 16; o; o >>= 1) d += __shfl_xor_sync(~0u, d, o);
        if (lane == 0) sd[j] = d;
    }
    __syncthreads();
    float a_di2 = 0.f, a_si2 = 0.f, a_disi = 0.f;
    float a_c2[20], a_dc[20];
#pragma unroll
    for (int c = 0; c < 20; c++) { a_c2[c] = 0.f; a_dc[c] = 0.f; }
    for (int l = t; l < 1019; l += 256) {
        const float* Srow = g_S + ((long)b*1024 + l)*22;
        float di = Srow[0];
        float si = Srow[1];
        a_di2 += di*di; a_si2 += si*si; a_disi += di*si;
#pragma unroll
        for (int c = 0; c < 20; c++) {
            float ci = Srow[2+c];
            a_c2[c] += ci*ci; a_dc[c] += di*ci;
        }
    }
    __shared__ float rs[43][8];
    float vals[43];
    vals[0] = a_di2; vals[1] = a_si2; vals[2] = a_disi;
#pragma unroll
    for (int c = 0; c < 20; c++) { vals[3+c] = a_c2[c]; vals[23+c] = a_dc[c]; }
#pragma unroll
    for (int k = 0; k < 43; k++) {
        float v = vals[k];
        for (int o = 16; o; o >>= 1) v += __shfl_xor_sync(~0u, v, o);
        if (lane == 0) rs[k][w] = v;
    }
    __syncthreads();
    if (t < 43) {
        float v = 0.f;
        for (int i = 0; i < 8; i++) v += rs[t][i];
        rs[t][0] = v;
    }
    __syncthreads();
    double dn2 = g_embn2d[b*22 + 0];
    float nd = fmaxf(sqrtf(rs[0][0]), 1e-8f);
    if (t == 0) {
        float ns = fmaxf(sqrtf(rs[1][0]), 1e-8f);
        out[80 + b] = __fadd_rn(g_sspd[b], rs[2][0]/(nd*ns));
    }
    if (t < 20) {
        double cn2 = g_embn2d[b*22 + 2 + t];
        double pd = pdist_d(cn2, dn2, sd[2 + t]);
        float nc = fmaxf(sqrtf(rs[3 + t][0]), 1e-8f);
        out[b*20 + t] = (float)(-pd*pd) + rs[23 + t][0]/(nd*nc);
    }
}

// ---------------- launch ----------------
extern "C" void kernel_launch(void* const* d_in, const int* in_sizes, int n_in,
                              void* d_out, int out_size) {
    const float* text = (const float*)d_in[0];
    const float* summ = (const float*)d_in[1];
    const float* cand = (const float*)d_in[2];
    const float* W_d  = (const float*)d_in[3];
    const float* W_s  = (const float*)d_in[4];
    const float* W_c  = (const float*)d_in[5];
    const float* W_p  = (const float*)d_in[6];
    const float* cw1  = (const float*)d_in[7];
    const float* cb1  = (const float*)d_in[8];
    const float* cw2  = (const float*)d_in[9];
    const float* cb2  = (const float*)d_in[10];
    float* out = (float*)d_out;

    void *p_gram, *p_dwe;
    cudaGetSymbolAddress(&p_gram, g_gram);
    cudaGetSymbolAddress(&p_dwe,  g_dweraw);

    // 1) max over summary / candidate sequence dims
    maxk<<<252, 256>>>(summ, cand);

    // 2) all small GEMMs as per-row chains; doc/summary rows dual-write raws
    rowgemm<<<88, 128>>>(text, W_d, W_s, W_c);

    // 3) tf32 tensor-core GEMMs: y2 + y1 in one launch (BN=128 -> 4 n-blocks)
    TP3 ta;
    ta.g[0] = { text, cw2, cb2, (float*)p_gram,
                2036, 1536, 509, 512L*768, 768, 768, 1019, 510, 1 };
    ta.g[1] = { text, cw1, cb1, (float*)p_gram,
                2040, 768,  510, 512L*768, 768, 768, 1019, 0,   1 };
    ta.g[2] = ta.g[1];
    ta.end[0] = 64; ta.end[1] = 128; ta.end[2] = 128;
    gemmT<<<128, 256>>>(ta);

    // 4) doc_word raw = gram @ W_p  (tf32)
    TP3 tw;
    tw.g[0] = { (float*)p_gram, W_p, nullptr, (float*)p_dwe,
                4076, 512, 1019, 1019L*512, 512, 0, 1019, 0, 0 };
    tw.g[1] = tw.g[0]; tw.g[2] = tw.g[0];
    tw.end[0] = 128; tw.end[1] = 128; tw.end[2] = 128;
    gemmT<<<128, 256>>>(tw);

    // 5) bit-replicated summary-doc pdist from the stored raw vectors
    emu_rest<<<4, 512>>>();

    // 6) expmap0 on 88 small embeddings (in place) + exact double norms
    epi_small<<<88, 128>>>();

    // 7) fused norm + 22 dots + fp32 inverse pdists per word
    rowops<<<dim3(4,64), 256>>>();

    // 8) cos_sim reductions + direct pdists (out0: double; out1: replicated)
    finalk<<<4, 256>>>(out);
}

// round 13
// speedup vs baseline: 1.6166x; 1.6166x over previous
#include <cuda_runtime.h>
#include <math.h>
#include <stdint.h>

#define SC   0.94868329805051381f
#define SCD  0.94868329805051380976
#define MAXND (0.996/0.94868329805051380976)

#define SCF   ((float)0.94868329805051380976)
#define MAXNF ((float)(0.996/0.94868329805051380976))
#define CLIPF ((float)(1.0 - 1e-7))
#define T2F   ((float)(2.0/0.94868329805051380976))

// ---------------- scratch ----------------
__device__ float  g_embs[4*22*512];
__device__ double g_embn2d[4*22];
__device__ float  g_gram[4*1019*512];
__device__ float  g_dweraw[4*1019*512];
__device__ float  g_S[4*1024*22];
__device__ float  g_sspd[4];
__device__ float  g_emud[4*512];
__device__ float  g_emus[4*512];

// ---------------- pdist helpers ----------------
__device__ __forceinline__ double pdist_z(double x2, double y2, double xy) {
    double A   = 1.0 - 1.8*xy + 0.9*y2;
    double B   = 1.0 - 0.9*x2;
    double den = 1.0 - 1.8*xy + 0.81*x2*y2;
    den = fmax(den, 1e-15);
    double num2 = A*A*x2 - 2.0*A*B*xy + B*B*y2;
    double nd2  = num2/(den*den);
    double n    = sqrt(fmax(nd2, 1e-30));
    return fmin(SCD*n, 1.0 - 1e-7);
}
__device__ __forceinline__ double pdist_d(double x2, double y2, double xy) {
    return (2.0/SCD)*atanh(pdist_z(x2, y2, xy));
}
__device__ __forceinline__ float pdist_wf(float x2, float y2, float xy) {
    float A   = 1.f - 1.8f*xy + 0.9f*y2;
    float B   = 1.f - 0.9f*x2;
    float den = fmaxf(1.f - 1.8f*xy + 0.81f*x2*y2, 1e-15f);
    float num2 = A*A*x2 - 2.f*A*B*xy + B*B*y2;
    float nd2  = num2/(den*den);
    float n    = sqrtf(fmaxf(nd2, 1e-30f));
    float z    = fminf(SC*n, 1.f - 1e-7f);
    return (2.f/SC)*atanhf(z);
}

// ====== fused: max-reduce + per-row chain GEMM + expmap0 (bit-identical) =====
// 88 blocks: 0..79 cand, 80..83 doc (dual-write raw), 84..87 summary (dual).
__global__ __launch_bounds__(128) void rowgemm(
    const float* __restrict__ text, const float* __restrict__ summ,
    const float* __restrict__ cand,
    const float* __restrict__ Wd, const float* __restrict__ Ws,
    const float* __restrict__ Wc)
{
    int r = blockIdx.x, t = threadIdx.x;
    __shared__ float sa[768];
    const float* B; float* C; float* C2 = nullptr; int erow;
    if (r < 80) {
        const float* p = cand + (long)r*128*768;
        for (int h = t; h < 768; h += 128) {
            float m = -3.4e38f;
#pragma unroll 4
            for (int l = 0; l < 128; l++) m = fmaxf(m, p[(long)l*768 + h]);
            sa[h] = m;
        }
        B = Wc;
        erow = (r/20)*22 + 2 + (r%20);
        C = g_embs + (long)erow*512;
    } else if (r < 84) {
        int b = r - 80;
        const float* p = text + (long)b*512*768;
        for (int h = t; h < 768; h += 128) sa[h] = p[h];
        B = Wd; erow = b*22;
        C = g_embs + (long)erow*512; C2 = g_emud + b*512;
    } else {
        int b = r - 84;
        const float* p = summ + (long)b*128*768;
        for (int h = t; h < 768; h += 128) {
            float m = -3.4e38f;
#pragma unroll 4
            for (int l = 0; l < 128; l++) m = fmaxf(m, p[(long)l*768 + h]);
            sa[h] = m;
        }
        B = Ws; erow = b*22 + 1;
        C = g_embs + (long)erow*512; C2 = g_emus + b*512;
    }
    __syncthreads();
    int c = t*4;
    float a0 = 0.f, a1 = 0.f, a2 = 0.f, a3 = 0.f;
    for (int k = 0; k < 768; k++) {
        float4 bv = *(const float4*)(B + (long)k*512 + c);
        float ak = sa[k];
        a0 = __fmaf_rn(ak, bv.x, a0);
        a1 = __fmaf_rn(ak, bv.y, a1);
        a2 = __fmaf_rn(ak, bv.z, a2);
        a3 = __fmaf_rn(ak, bv.w, a3);
    }
    if (C2) { C2[c] = a0; C2[c+1] = a1; C2[c+2] = a2; C2[c+3] = a3; }
    // epilogue floats exactly as before (acc + 0.0f)
    float o0 = a0 + 0.f, o1 = a1 + 0.f, o2 = a2 + 0.f, o3 = a3 + 0.f;
    // ---- fused expmap0: replicate epi_small's exact double reduction order
    double s = (double)o0*o0 + (double)o1*o1 + (double)o2*o2 + (double)o3*o3;
    for (int o = 16; o; o >>= 1) s += __shfl_xor_sync(~0u, s, o);
    __shared__ double sw[4];
    if ((t & 31) == 0) sw[t >> 5] = s;
    __syncthreads();
    s = sw[0] + sw[1] + sw[2] + sw[3];
    double n = sqrt(fmax(s, 1e-30));
    double scn = SCD*n;
    double tt = tanh(scn);
    double f = tt/scn;
    double gn = tt/SCD;
    if (gn > MAXND) f *= MAXND/gn;
    float ff = (float)f;
    C[c]   = o0*ff; C[c+1] = o1*ff; C[c+2] = o2*ff; C[c+3] = o3*ff;
    if (t == 0) { double xn = fmin(gn, MAXND); g_embn2d[erow] = xn*xn; }
}

// ================= tf32 tensor-core GEMM (R11 version: BM=128 BN=64) =========
struct GP {
    const float* A; const float* B; const float* bias; float* C;
    int M, K, RPB; long IB, IL, IO; int OB, OO, relu;
};
struct TP3 { GP g[3]; int end[3]; };

__device__ __forceinline__ float to_tf32(float x) {
    uint32_t r;
    asm("cvt.rna.tf32.f32 %0, %1;" : "=r"(r) : "f"(x));
    return __uint_as_float(r);
}

#define APAD 20
__global__ __launch_bounds__(256) void gemmT(TP3 ps) {
    __shared__ float As[2][128][APAD];
    __shared__ float Bs[2][64][APAD];
    int id = blockIdx.x;
    int pi = 0, base = 0;
#pragma unroll
    for (int q = 0; q < 3; q++) {
        if (id >= ps.end[q]) { pi = q + 1; base = ps.end[q]; }
    }
    GP p = ps.g[pi];
    int bx = id - base;
    int bm = (bx >> 3) * 128, bn = (bx & 7) * 64;
    int t = threadIdx.x;
    int w = t >> 5, lane = t & 31;
    int g = lane >> 2, tig = lane & 3;
    int wm = w & 3, wn = w >> 2;

    int r0i = t >> 2, r1i = (t + 256) >> 2;
    int kq0 = (t & 3) * 4;
    int gr0 = bm + r0i; if (gr0 >= p.M) gr0 = p.M - 1;
    int gr1 = bm + r1i; if (gr1 >= p.M) gr1 = p.M - 1;
    int ab0 = gr0 / p.RPB, al0 = gr0 - ab0 * p.RPB;
    int ab1 = gr1 / p.RPB, al1 = gr1 - ab1 * p.RPB;
    const float* Ap0 = p.A + ab0 * p.IB + (long)al0 * p.IL + p.IO + kq0;
    const float* Ap1 = p.A + ab1 * p.IB + (long)al1 * p.IL + p.IO + kq0;
    int bkk = t >> 4, bn4 = (t & 15) << 2;
    const float* Bp = p.B + (long)bkk * 512 + bn + bn4;

    float acc[2][4][4];
#pragma unroll
    for (int i = 0; i < 2; i++)
#pragma unroll
        for (int j = 0; j < 4; j++)
#pragma unroll
            for (int r = 0; r < 4; r++) acc[i][j][r] = 0.f;

    int ntiles = p.K >> 4;
    float4 pa0 = *(const float4*)(Ap0);
    float4 pa1 = *(const float4*)(Ap1);
    float4 pb  = *(const float4*)(Bp);
    {
        float* a = &As[0][r0i][kq0];
        a[0]=to_tf32(pa0.x); a[1]=to_tf32(pa0.y); a[2]=to_tf32(pa0.z); a[3]=to_tf32(pa0.w);
        float* a2 = &As[0][r1i][kq0];
        a2[0]=to_tf32(pa1.x); a2[1]=to_tf32(pa1.y); a2[2]=to_tf32(pa1.z); a2[3]=to_tf32(pa1.w);
        Bs[0][bn4+0][bkk]=to_tf32(pb.x); Bs[0][bn4+1][bkk]=to_tf32(pb.y);
        Bs[0][bn4+2][bkk]=to_tf32(pb.z); Bs[0][bn4+3][bkk]=to_tf32(pb.w);
    }
    __syncthreads();

    for (int tile = 0; tile < ntiles; tile++) {
        int buf = tile & 1;
        if (tile + 1 < ntiles) {
            long ko = (long)(tile + 1) * 16;
            pa0 = *(const float4*)(Ap0 + ko);
            pa1 = *(const float4*)(Ap1 + ko);
            pb  = *(const float4*)(Bp + ko * 512);
        }
#pragma unroll
        for (int ks = 0; ks < 16; ks += 8) {
            uint32_t af[2][4];
#pragma unroll
            for (int mt = 0; mt < 2; mt++) {
                int r = wm*32 + mt*16 + g;
                af[mt][0] = __float_as_uint(As[buf][r    ][ks + tig]);
                af[mt][1] = __float_as_uint(As[buf][r + 8][ks + tig]);
                af[mt][2] = __float_as_uint(As[buf][r    ][ks + tig + 4]);
                af[mt][3] = __float_as_uint(As[buf][r + 8][ks + tig + 4]);
            }
            uint32_t bfr[4][2];
#pragma unroll
            for (int nt = 0; nt < 4; nt++) {
                int n = wn*32 + nt*8 + g;
                bfr[nt][0] = __float_as_uint(Bs[buf][n][ks + tig]);
                bfr[nt][1] = __float_as_uint(Bs[buf][n][ks + tig + 4]);
            }
#pragma unroll
            for (int mt = 0; mt < 2; mt++)
#pragma unroll
                for (int nt = 0; nt < 4; nt++) {
                    asm volatile(
                        "mma.sync.aligned.m16n8k8.row.col.f32.tf32.tf32.f32 "
                        "{%0,%1,%2,%3}, {%4,%5,%6,%7}, {%8,%9}, {%0,%1,%2,%3};"
                        : "+f"(acc[mt][nt][0]), "+f"(acc[mt][nt][1]),
                          "+f"(acc[mt][nt][2]), "+f"(acc[mt][nt][3])
                        : "r"(af[mt][0]), "r"(af[mt][1]), "r"(af[mt][2]), "r"(af[mt][3]),
                          "r"(bfr[nt][0]), "r"(bfr[nt][1]));
                }
        }
        if (tile + 1 < ntiles) {
            int nb = buf ^ 1;
            float* a = &As[nb][r0i][kq0];
            a[0]=to_tf32(pa0.x); a[1]=to_tf32(pa0.y); a[2]=to_tf32(pa0.z); a[3]=to_tf32(pa0.w);
            float* a2 = &As[nb][r1i][kq0];
            a2[0]=to_tf32(pa1.x); a2[1]=to_tf32(pa1.y); a2[2]=to_tf32(pa1.z); a2[3]=to_tf32(pa1.w);
            Bs[nb][bn4+0][bkk]=to_tf32(pb.x); Bs[nb][bn4+1][bkk]=to_tf32(pb.y);
            Bs[nb][bn4+2][bkk]=to_tf32(pb.z); Bs[nb][bn4+3][bkk]=to_tf32(pb.w);
            __syncthreads();
        }
    }

#pragma unroll
    for (int mt = 0; mt < 2; mt++) {
#pragma unroll
        for (int half = 0; half < 2; half++) {
            int gm = bm + wm*32 + mt*16 + g + half*8;
            if (gm < p.M) {
                int ob = gm / p.RPB, ol = gm - ob*p.RPB;
                float* Crow = p.C + ((long)ob*p.OB + p.OO + ol)*512;
#pragma unroll
                for (int nt = 0; nt < 4; nt++) {
                    int col = bn + wn*32 + nt*8 + 2*tig;
                    float b0 = p.bias ? p.bias[col]   : 0.f;
                    float b1 = p.bias ? p.bias[col+1] : 0.f;
                    float v0 = acc[mt][nt][half*2+0] + b0;
                    float v1 = acc[mt][nt][half*2+1] + b1;
                    if (p.relu) { v0 = fmaxf(v0, 0.f); v1 = fmaxf(v1, 0.f); }
                    Crow[col]   = v0;
                    Crow[col+1] = v1;
                }
            }
        }
    }
}

// =============== bit-replication of the reference summary-doc pdist ==========
__device__ __forceinline__ float xla_red_sq(const float* v, int lane) {
    float a = 0.f;
    for (int m = 0; m < 16; m++) a = __fadd_rn(a, __fmul_rn(v[lane + 32*m], v[lane + 32*m]));
    for (int off = 16; off; off >>= 1) a = __fadd_rn(a, __shfl_down_sync(0xffffffffu, a, off));
    return __shfl_sync(0xffffffffu, a, 0);
}
__device__ __forceinline__ float xla_red_dotneg(const float* v1, const float* v2, int lane) {
    float a = 0.f;
    for (int m = 0; m < 16; m++) {
        int i = lane + 32*m;
        a = __fadd_rn(a, __fmul_rn(-v1[i], v2[i]));
    }
    for (int off = 16; off; off >>= 1) a = __fadd_rn(a, __shfl_down_sync(0xffffffffu, a, off));
    return __shfl_sync(0xffffffffu, a, 0);
}

__global__ __launch_bounds__(512) void emu_rest() {
    int b = blockIdx.x, t = threadIdx.x;
    __shared__ float ud[512], us[512], gd[512], gs[512], xd[512], xs[512], dv[512];
    __shared__ float sc[10];
    ud[t] = g_emud[b*512 + t];
    us[t] = g_emus[b*512 + t];
    __syncthreads();
    if (t < 32) {
        float n2 = xla_red_sq(ud, t);
        float nu = fmaxf(__fsqrt_rn(fmaxf(n2, 1e-30f)), 1e-15f);
        float scn = __fmul_rn(SCF, nu);
        if (t == 0) { sc[0] = scn; sc[2] = (float)tanh((double)scn); }
        n2 = xla_red_sq(us, t);
        nu = fmaxf(__fsqrt_rn(fmaxf(n2, 1e-30f)), 1e-15f);
        scn = __fmul_rn(SCF, nu);
        if (t == 0) { sc[1] = scn; sc[3] = (float)tanh((double)scn); }
    }
    __syncthreads();
    gd[t] = __fdiv_rn(__fmul_rn(sc[2], ud[t]), sc[0]);
    gs[t] = __fdiv_rn(__fmul_rn(sc[3], us[t]), sc[1]);
    __syncthreads();
    if (t < 32) {
        float n2 = xla_red_sq(gd, t);
        float ng = fmaxf(__fsqrt_rn(fmaxf(n2, 1e-30f)), 1e-15f);
        if (t == 0) sc[4] = ng;
        n2 = xla_red_sq(gs, t);
        ng = fmaxf(__fsqrt_rn(fmaxf(n2, 1e-30f)), 1e-15f);
        if (t == 0) sc[5] = ng;
    }
    __syncthreads();
    xd[t] = (sc[4] > MAXNF) ? __fmul_rn(__fdiv_rn(gd[t], sc[4]), MAXNF) : gd[t];
    xs[t] = (sc[5] > MAXNF) ? __fmul_rn(__fdiv_rn(gs[t], sc[5]), MAXNF) : gs[t];
    __syncthreads();
    if (t < 32) {
        float x2 = xla_red_sq(xs, t);
        float y2 = xla_red_sq(xd, t);
        float xy = xla_red_dotneg(xs, xd, t);
        if (t == 0) {
            float t18  = __fmul_rn(1.8f, xy);
            float base = __fadd_rn(1.0f, t18);
            sc[6] = __fadd_rn(base, __fmul_rn(0.9f, y2));
            sc[7] = __fsub_rn(1.0f, __fmul_rn(0.9f, x2));
            float den = __fadd_rn(base, __fmul_rn(__fmul_rn(0.81f, x2), y2));
            sc[8] = fmaxf(den, 1e-15f);
        }
    }
    __syncthreads();
    {
        float xm  = -xs[t];
        float num = __fadd_rn(__fmul_rn(sc[6], xm), __fmul_rn(sc[7], xd[t]));
        dv[t] = __fdiv_rn(num, sc[8]);
    }
    __syncthreads();
    if (t < 32) {
        float n2 = xla_red_sq(dv, t);
        if (t == 0) {
            float nn = __fsqrt_rn(fmaxf(n2, 1e-30f));
            float z  = __fmul_rn(SCF, nn);
            z = fminf(z, CLIPF); z = fmaxf(z, -CLIPF);
            float at = (float)atanh((double)z);
            float pd = __fmul_rn(T2F, at);
            g_sspd[b] = -__fmul_rn(pd, pd);
        }
    }
}

// ------- fused expmap0(norm) + 22 dots + fp32 inverse pdist per word row -----
__global__ __launch_bounds__(256) void rowops() {
    int b = blockIdx.x;
    int l0 = blockIdx.y * 16;
    __shared__ float  se[22*512];
    __shared__ float  sdots[16][22];
    __shared__ float  sf[16];
    __shared__ float  sx2[16];
    __shared__ float  sy2[22];
    int t = threadIdx.x;
    for (int i = t; i < 11264; i += 256) se[i] = g_embs[(long)b*11264 + i];
    if (t < 22) sy2[t] = (float)g_embn2d[b*22 + t];
    __syncthreads();
    int r = t >> 4, cg = t & 15;
    int l = l0 + r;
    int lv = (l < 1019) ? l : 1018;
    const float* u = g_dweraw + ((long)b*1019 + lv)*512;
    float4 ur[8];
#pragma unroll
    for (int i = 0; i < 8; i++) ur[i] = ((const float4*)u)[cg + i*16];
    float s = 0.f;
#pragma unroll
    for (int i = 0; i < 8; i++)
        s += ur[i].x*ur[i].x + ur[i].y*ur[i].y + ur[i].z*ur[i].z + ur[i].w*ur[i].w;
    for (int o = 8; o; o >>= 1) s += __shfl_xor_sync(~0u, s, o);
    {
        float n = sqrtf(fmaxf(s, 1e-30f));
        float scn = SC*n, tt = tanhf(scn);
        float f = tt/scn, gn = tt/SC;
        if (gn > MAXNF) f *= MAXNF/gn;
        if (cg == 0) {
            sf[r] = f;
            float xn = fminf(gn, MAXNF);
            sx2[r] = xn*xn;
        }
    }
    for (int j = 0; j < 22; j++) {
        const float4* e = (const float4*)(se + j*512);
        float d = 0.f;
#pragma unroll
        for (int i = 0; i < 8; i++) {
            float4 ev = e[cg + i*16];
            d += ur[i].x*ev.x + ur[i].y*ev.y + ur[i].z*ev.z + ur[i].w*ev.w;
        }
        for (int o = 8; o; o >>= 1) d += __shfl_xor_sync(~0u, d, o);
        if (cg == 0) sdots[r][j] = d;
    }
    __syncthreads();
    for (int item = t; item < 352; item += 256) {
        int r2 = item/22, j = item - r2*22;
        int l2 = l0 + r2;
        if (l2 < 1019) {
            float xy = sf[r2] * sdots[r2][j];
            float pd = pdist_wf(sx2[r2], sy2[j], xy);
            g_S[((long)b*1024 + l2)*22 + j] = 1.f/pd;
        }
    }
}

// ---------------- final scoring ----------------
__global__ __launch_bounds__(256) void finalk(float* __restrict__ out) {
    int b = blockIdx.x, t = threadIdx.x;
    int w = t >> 5, lane = t & 31;
    __shared__ double sd[22];
    const float4* e0 = (const float4*)(g_embs + (long)b*11264);
    for (int j = w; j < 22; j += 8) {
        const float4* ej = (const float4*)(g_embs + (long)b*11264 + j*512);
        double d = 0.0;
        for (int i = lane; i < 128; i += 32) {
            float4 a = e0[i], c = ej[i];
            d += (double)a.x*c.x + (double)a.y*c.y + (double)a.z*c.z + (double)a.w*c.w;
        }
        for (int o = 16; o; o >>= 1) d += __shfl_xor_sync(~0u, d, o);
        if (lane == 0) sd[j] = d;
    }
    __syncthreads();
    float a_di2 = 0.f, a_si2 = 0.f, a_disi = 0.f;
    float a_c2[20], a_dc[20];
#pragma unroll
    for (int c = 0; c < 20; c++) { a_c2[c] = 0.f; a_dc[c] = 0.f; }
    for (int l = t; l < 1019; l += 256) {
        const float* Srow = g_S + ((long)b*1024 + l)*22;
        float di = Srow[0];
        float si = Srow[1];
        a_di2 += di*di; a_si2 += si*si; a_disi += di*si;
#pragma unroll
        for (int c = 0; c < 20; c++) {
            float ci = Srow[2+c];
            a_c2[c] += ci*ci; a_dc[c] += di*ci;
        }
    }
    __shared__ float rs[43][8];
    float vals[43];
    vals[0] = a_di2; vals[1] = a_si2; vals[2] = a_disi;
#pragma unroll
    for (int c = 0; c < 20; c++) { vals[3+c] = a_c2[c]; vals[23+c] = a_dc[c]; }
#pragma unroll
    for (int k = 0; k < 43; k++) {
        float v = vals[k];
        for (int o = 16; o; o >>= 1) v += __shfl_xor_sync(~0u, v, o);
        if (lane == 0) rs[k][w] = v;
    }
    __syncthreads();
    if (t < 43) {
        float v = 0.f;
        for (int i = 0; i < 8; i++) v += rs[t][i];
        rs[t][0] = v;
    }
    __syncthreads();
    double dn2 = g_embn2d[b*22 + 0];
    float nd = fmaxf(sqrtf(rs[0][0]), 1e-8f);
    if (t == 0) {
        float ns = fmaxf(sqrtf(rs[1][0]), 1e-8f);
        out[80 + b] = __fadd_rn(g_sspd[b], rs[2][0]/(nd*ns));
    }
    if (t < 20) {
        double cn2 = g_embn2d[b*22 + 2 + t];
        double pd = pdist_d(cn2, dn2, sd[2 + t]);
        float nc = fmaxf(sqrtf(rs[3 + t][0]), 1e-8f);
        out[b*20 + t] = (float)(-pd*pd) + rs[23 + t][0]/(nd*nc);
    }
}

// ---------------- launch ----------------
extern "C" void kernel_launch(void* const* d_in, const int* in_sizes, int n_in,
                              void* d_out, int out_size) {
    const float* text = (const float*)d_in[0];
    const float* summ = (const float*)d_in[1];
    const float* cand = (const float*)d_in[2];
    const float* W_d  = (const float*)d_in[3];
    const float* W_s  = (const float*)d_in[4];
    const float* W_c  = (const float*)d_in[5];
    const float* W_p  = (const float*)d_in[6];
    const float* cw1  = (const float*)d_in[7];
    const float* cb1  = (const float*)d_in[8];
    const float* cw2  = (const float*)d_in[9];
    const float* cb2  = (const float*)d_in[10];
    float* out = (float*)d_out;

    void *p_gram, *p_dwe;
    cudaGetSymbolAddress(&p_gram, g_gram);
    cudaGetSymbolAddress(&p_dwe,  g_dweraw);

    // side stream + fork/join events (created once, on the uncaptured
    // correctness call; replayed identically under capture)
    static cudaStream_t s2 = nullptr;
    static cudaEvent_t evF = nullptr, evJ = nullptr;
    if (s2 == nullptr) {
        cudaStreamCreateWithFlags(&s2, cudaStreamNonBlocking);
        cudaEventCreateWithFlags(&evF, cudaEventDisableTiming);
        cudaEventCreateWithFlags(&evJ, cudaEventDisableTiming);
    }

    // fork side chain off the main (capture) stream
    cudaEventRecord(evF, 0);
    cudaStreamWaitEvent(s2, evF, 0);

    // side chain: fused max+GEMM+expmap0 for 88 embeddings, then out1 emulation
    rowgemm<<<88, 128, 0, s2>>>(text, summ, cand, W_d, W_s, W_c);
    emu_rest<<<4, 512, 0, s2>>>();
    cudaEventRecord(evJ, s2);

    // main chain: tf32 GEMMs (y2+y1, then W_p)
    TP3 ta;
    ta.g[0] = { text, cw2, cb2, (float*)p_gram,
                2036, 1536, 509, 512L*768, 768, 768, 1019, 510, 1 };
    ta.g[1] = { text, cw1, cb1, (float*)p_gram,
                2040, 768,  510, 512L*768, 768, 768, 1019, 0,   1 };
    ta.g[2] = ta.g[1];
    ta.end[0] = 128; ta.end[1] = 256; ta.end[2] = 256;
    gemmT<<<256, 256>>>(ta);

    TP3 tw;
    tw.g[0] = { (float*)p_gram, W_p, nullptr, (float*)p_dwe,
                4076, 512, 1019, 1019L*512, 512, 0, 1019, 0, 0 };
    tw.g[1] = tw.g[0]; tw.g[2] = tw.g[0];
    tw.end[0] = 256; tw.end[1] = 256; tw.end[2] = 256;
    gemmT<<<256, 256>>>(tw);

    // join: rowops needs g_dweraw (main) + g_embs/g_embn2d (side)
    cudaStreamWaitEvent(0, evJ, 0);

    rowops<<<dim3(4,64), 256>>>();
    finalk<<<4, 256>>>(out);
}

// round 15
// speedup vs baseline: 1.7315x; 1.0711x over previous
#include <cuda_runtime.h>
#include <cuda_bf16.h>
#include <math.h>
#include <stdint.h>

#define SC   0.94868329805051381f
#define SCD  0.94868329805051380976
#define MAXND (0.996/0.94868329805051380976)

#define SCF   ((float)0.94868329805051380976)
#define MAXNF ((float)(0.996/0.94868329805051380976))
#define CLIPF ((float)(1.0 - 1e-7))
#define T2F   ((float)(2.0/0.94868329805051380976))

// ---------------- scratch ----------------
__device__ float  g_embs[4*22*512];
__device__ double g_embn2d[4*22];
__device__ float  g_gram[4*1019*512];
__device__ float  g_dweraw[4*1019*512];
__device__ float  g_S[4*1024*22];
__device__ float  g_sspd[4];
__device__ float  g_emud[4*512];
__device__ float  g_emus[4*512];

// ---------------- pdist helpers ----------------
__device__ __forceinline__ double pdist_z(double x2, double y2, double xy) {
    double A   = 1.0 - 1.8*xy + 0.9*y2;
    double B   = 1.0 - 0.9*x2;
    double den = 1.0 - 1.8*xy + 0.81*x2*y2;
    den = fmax(den, 1e-15);
    double num2 = A*A*x2 - 2.0*A*B*xy + B*B*y2;
    double nd2  = num2/(den*den);
    double n    = sqrt(fmax(nd2, 1e-30));
    return fmin(SCD*n, 1.0 - 1e-7);
}
__device__ __forceinline__ double pdist_d(double x2, double y2, double xy) {
    return (2.0/SCD)*atanh(pdist_z(x2, y2, xy));
}
__device__ __forceinline__ float pdist_wf(float x2, float y2, float xy) {
    float A   = 1.f - 1.8f*xy + 0.9f*y2;
    float B   = 1.f - 0.9f*x2;
    float den = fmaxf(1.f - 1.8f*xy + 0.81f*x2*y2, 1e-15f);
    float num2 = A*A*x2 - 2.f*A*B*xy + B*B*y2;
    float nd2  = num2/(den*den);
    float n    = sqrtf(fmaxf(nd2, 1e-30f));
    float z    = fminf(SC*n, 1.f - 1e-7f);
    return (2.f/SC)*atanhf(z);
}

// ====== fused: max-reduce + per-row chain GEMM + expmap0 (bit-identical) =====
__global__ __launch_bounds__(128) void rowgemm(
    const float* __restrict__ text, const float* __restrict__ summ,
    const float* __restrict__ cand,
    const float* __restrict__ Wd, const float* __restrict__ Ws,
    const float* __restrict__ Wc)
{
    int r = blockIdx.x, t = threadIdx.x;
    __shared__ float sa[768];
    const float* B; float* C; float* C2 = nullptr; int erow;
    if (r < 80) {
        const float* p = cand + (long)r*128*768;
        for (int h = t; h < 768; h += 128) {
            float m = -3.4e38f;
#pragma unroll 4
            for (int l = 0; l < 128; l++) m = fmaxf(m, p[(long)l*768 + h]);
            sa[h] = m;
        }
        B = Wc;
        erow = (r/20)*22 + 2 + (r%20);
        C = g_embs + (long)erow*512;
    } else if (r < 84) {
        int b = r - 80;
        const float* p = text + (long)b*512*768;
        for (int h = t; h < 768; h += 128) sa[h] = p[h];
        B = Wd; erow = b*22;
        C = g_embs + (long)erow*512; C2 = g_emud + b*512;
    } else {
        int b = r - 84;
        const float* p = summ + (long)b*128*768;
        for (int h = t; h < 768; h += 128) {
            float m = -3.4e38f;
#pragma unroll 4
            for (int l = 0; l < 128; l++) m = fmaxf(m, p[(long)l*768 + h]);
            sa[h] = m;
        }
        B = Ws; erow = b*22 + 1;
        C = g_embs + (long)erow*512; C2 = g_emus + b*512;
    }
    __syncthreads();
    int c = t*4;
    float a0 = 0.f, a1 = 0.f, a2 = 0.f, a3 = 0.f;
    for (int k = 0; k < 768; k++) {
        float4 bv = *(const float4*)(B + (long)k*512 + c);
        float ak = sa[k];
        a0 = __fmaf_rn(ak, bv.x, a0);
        a1 = __fmaf_rn(ak, bv.y, a1);
        a2 = __fmaf_rn(ak, bv.z, a2);
        a3 = __fmaf_rn(ak, bv.w, a3);
    }
    if (C2) { C2[c] = a0; C2[c+1] = a1; C2[c+2] = a2; C2[c+3] = a3; }
    float o0 = a0 + 0.f, o1 = a1 + 0.f, o2 = a2 + 0.f, o3 = a3 + 0.f;
    double s = (double)o0*o0 + (double)o1*o1 + (double)o2*o2 + (double)o3*o3;
    for (int o = 16; o; o >>= 1) s += __shfl_xor_sync(~0u, s, o);
    __shared__ double sw[4];
    if ((t & 31) == 0) sw[t >> 5] = s;
    __syncthreads();
    s = sw[0] + sw[1] + sw[2] + sw[3];
    double n = sqrt(fmax(s, 1e-30));
    double scn = SCD*n;
    double tt = tanh(scn);
    double f = tt/scn;
    double gn = tt/SCD;
    if (gn > MAXND) f *= MAXND/gn;
    float ff = (float)f;
    C[c]   = o0*ff; C[c+1] = o1*ff; C[c+2] = o2*ff; C[c+3] = o3*ff;
    if (t == 0) { double xn = fmin(gn, MAXND); g_embn2d[erow] = xn*xn; }
}

// ================= bf16 tensor-core GEMM: BM=128 BN=64 BK=16 =================
struct GP {
    const float* A; const float* B; const float* bias; float* C;
    int M, K, RPB; long IB, IL, IO; int OB, OO, relu;
};
struct TP3 { GP g[3]; int end[3]; };

#define KP 24   // bf16 row pitch (48 bytes): conflict-free paired frag loads
__global__ __launch_bounds__(256) void gemmH(TP3 ps) {
    __shared__ __nv_bfloat16 As[2][128][KP];
    __shared__ __nv_bfloat16 Bs[2][64][KP];
    int id = blockIdx.x;
    int pi = 0, base = 0;
#pragma unroll
    for (int q = 0; q < 3; q++) {
        if (id >= ps.end[q]) { pi = q + 1; base = ps.end[q]; }
    }
    GP p = ps.g[pi];
    int bx = id - base;
    int bm = (bx >> 3) * 128, bn = (bx & 7) * 64;
    int t = threadIdx.x;
    int w = t >> 5, lane = t & 31;
    int g = lane >> 2, tig = lane & 3;
    int wm = w & 3, wn = w >> 2;          // 4 m-warps x 2 n-warps, 32x32 warp tile

    // A staging: thread -> row t>>1, k-octet (t&1)*8 (covers 128 x 16)
    int ar = t >> 1, kq = (t & 1) * 8;
    int gr = bm + ar; if (gr >= p.M) gr = p.M - 1;
    int ab = gr / p.RPB, al = gr - ab * p.RPB;
    const float* Ap = p.A + ab * p.IB + (long)al * p.IL + p.IO + kq;
    // B staging: thread -> k = t>>4, n-quad (t&15)*4 (covers 16 x 64)
    int bk = t >> 4, bn4 = (t & 15) << 2;
    const float* Bq = p.B + (long)bk * 512 + bn + bn4;

    float acc[2][4][4];
#pragma unroll
    for (int i = 0; i < 2; i++)
#pragma unroll
        for (int j = 0; j < 4; j++)
#pragma unroll
            for (int r = 0; r < 4; r++) acc[i][j][r] = 0.f;

    int ntiles = p.K >> 4;
    float4 pa0 = *(const float4*)(Ap);
    float4 pa1 = *(const float4*)(Ap + 4);
    float4 pb  = *(const float4*)(Bq);
    {
        __nv_bfloat162 c0 = __floats2bfloat162_rn(pa0.x, pa0.y);
        __nv_bfloat162 c1 = __floats2bfloat162_rn(pa0.z, pa0.w);
        __nv_bfloat162 c2 = __floats2bfloat162_rn(pa1.x, pa1.y);
        __nv_bfloat162 c3 = __floats2bfloat162_rn(pa1.z, pa1.w);
        uint4 pk = { *(uint32_t*)&c0, *(uint32_t*)&c1, *(uint32_t*)&c2, *(uint32_t*)&c3 };
        *(uint4*)&As[0][ar][kq] = pk;
        Bs[0][bn4+0][bk] = __float2bfloat16_rn(pb.x);
        Bs[0][bn4+1][bk] = __float2bfloat16_rn(pb.y);
        Bs[0][bn4+2][bk] = __float2bfloat16_rn(pb.z);
        Bs[0][bn4+3][bk] = __float2bfloat16_rn(pb.w);
    }
    __syncthreads();

    for (int tile = 0; tile < ntiles; tile++) {
        int buf = tile & 1;
        if (tile + 1 < ntiles) {
            long ko = (long)(tile + 1) * 16;
            pa0 = *(const float4*)(Ap + ko);
            pa1 = *(const float4*)(Ap + ko + 4);
            pb  = *(const float4*)(Bq + ko * 512);
        }
        {
            uint32_t af[2][4];
#pragma unroll
            for (int mt = 0; mt < 2; mt++) {
                int r = wm*32 + mt*16 + g;
                af[mt][0] = *(const uint32_t*)&As[buf][r    ][2*tig];
                af[mt][1] = *(const uint32_t*)&As[buf][r + 8][2*tig];
                af[mt][2] = *(const uint32_t*)&As[buf][r    ][2*tig + 8];
                af[mt][3] = *(const uint32_t*)&As[buf][r + 8][2*tig + 8];
            }
            uint32_t bfr[4][2];
#pragma unroll
            for (int nt = 0; nt < 4; nt++) {
                int n = wn*32 + nt*8 + g;
                bfr[nt][0] = *(const uint32_t*)&Bs[buf][n][2*tig];
                bfr[nt][1] = *(const uint32_t*)&Bs[buf][n][2*tig + 8];
            }
#pragma unroll
            for (int mt = 0; mt < 2; mt++)
#pragma unroll
                for (int nt = 0; nt < 4; nt++) {
                    asm volatile(
                        "mma.sync.aligned.m16n8k16.row.col.f32.bf16.bf16.f32 "
                        "{%0,%1,%2,%3}, {%4,%5,%6,%7}, {%8,%9}, {%0,%1,%2,%3};"
                        : "+f"(acc[mt][nt][0]), "+f"(acc[mt][nt][1]),
                          "+f"(acc[mt][nt][2]), "+f"(acc[mt][nt][3])
                        : "r"(af[mt][0]), "r"(af[mt][1]), "r"(af[mt][2]), "r"(af[mt][3]),
                          "r"(bfr[nt][0]), "r"(bfr[nt][1]));
                }
        }
        if (tile + 1 < ntiles) {
            int nb = buf ^ 1;
            __nv_bfloat162 c0 = __floats2bfloat162_rn(pa0.x, pa0.y);
            __nv_bfloat162 c1 = __floats2bfloat162_rn(pa0.z, pa0.w);
            __nv_bfloat162 c2 = __floats2bfloat162_rn(pa1.x, pa1.y);
            __nv_bfloat162 c3 = __floats2bfloat162_rn(pa1.z, pa1.w);
            uint4 pk = { *(uint32_t*)&c0, *(uint32_t*)&c1, *(uint32_t*)&c2, *(uint32_t*)&c3 };
            *(uint4*)&As[nb][ar][kq] = pk;
            Bs[nb][bn4+0][bk] = __float2bfloat16_rn(pb.x);
            Bs[nb][bn4+1][bk] = __float2bfloat16_rn(pb.y);
            Bs[nb][bn4+2][bk] = __float2bfloat16_rn(pb.z);
            Bs[nb][bn4+3][bk] = __float2bfloat16_rn(pb.w);
            __syncthreads();
        }
    }

#pragma unroll
    for (int mt = 0; mt < 2; mt++) {
#pragma unroll
        for (int half = 0; half < 2; half++) {
            int gm = bm + wm*32 + mt*16 + g + half*8;
            if (gm < p.M) {
                int ob = gm / p.RPB, ol = gm - ob*p.RPB;
                float* Crow = p.C + ((long)ob*p.OB + p.OO + ol)*512;
#pragma unroll
                for (int nt = 0; nt < 4; nt++) {
                    int col = bn + wn*32 + nt*8 + 2*tig;
                    float b0 = p.bias ? p.bias[col]   : 0.f;
                    float b1 = p.bias ? p.bias[col+1] : 0.f;
                    float v0 = acc[mt][nt][half*2+0] + b0;
                    float v1 = acc[mt][nt][half*2+1] + b1;
                    if (p.relu) { v0 = fmaxf(v0, 0.f); v1 = fmaxf(v1, 0.f); }
                    Crow[col]   = v0;
                    Crow[col+1] = v1;
                }
            }
        }
    }
}

// =============== bit-replication of the reference summary-doc pdist ==========
__device__ __forceinline__ float xla_red_sq(const float* v, int lane) {
    float a = 0.f;
    for (int m = 0; m < 16; m++) a = __fadd_rn(a, __fmul_rn(v[lane + 32*m], v[lane + 32*m]));
    for (int off = 16; off; off >>= 1) a = __fadd_rn(a, __shfl_down_sync(0xffffffffu, a, off));
    return __shfl_sync(0xffffffffu, a, 0);
}
__device__ __forceinline__ float xla_red_dotneg(const float* v1, const float* v2, int lane) {
    float a = 0.f;
    for (int m = 0; m < 16; m++) {
        int i = lane + 32*m;
        a = __fadd_rn(a, __fmul_rn(-v1[i], v2[i]));
    }
    for (int off = 16; off; off >>= 1) a = __fadd_rn(a, __shfl_down_sync(0xffffffffu, a, off));
    return __shfl_sync(0xffffffffu, a, 0);
}

__global__ __launch_bounds__(512) void emu_rest() {
    int b = blockIdx.x, t = threadIdx.x;
    __shared__ float ud[512], us[512], gd[512], gs[512], xd[512], xs[512], dv[512];
    __shared__ float sc[10];
    ud[t] = g_emud[b*512 + t];
    us[t] = g_emus[b*512 + t];
    __syncthreads();
    if (t < 32) {
        float n2 = xla_red_sq(ud, t);
        float nu = fmaxf(__fsqrt_rn(fmaxf(n2, 1e-30f)), 1e-15f);
        float scn = __fmul_rn(SCF, nu);
        if (t == 0) { sc[0] = scn; sc[2] = (float)tanh((double)scn); }
        n2 = xla_red_sq(us, t);
        nu = fmaxf(__fsqrt_rn(fmaxf(n2, 1e-30f)), 1e-15f);
        scn = __fmul_rn(SCF, nu);
        if (t == 0) { sc[1] = scn; sc[3] = (float)tanh((double)scn); }
    }
    __syncthreads();
    gd[t] = __fdiv_rn(__fmul_rn(sc[2], ud[t]), sc[0]);
    gs[t] = __fdiv_rn(__fmul_rn(sc[3], us[t]), sc[1]);
    __syncthreads();
    if (t < 32) {
        float n2 = xla_red_sq(gd, t);
        float ng = fmaxf(__fsqrt_rn(fmaxf(n2, 1e-30f)), 1e-15f);
        if (t == 0) sc[4] = ng;
        n2 = xla_red_sq(gs, t);
        ng = fmaxf(__fsqrt_rn(fmaxf(n2, 1e-30f)), 1e-15f);
        if (t == 0) sc[5] = ng;
    }
    __syncthreads();
    xd[t] = (sc[4] > MAXNF) ? __fmul_rn(__fdiv_rn(gd[t], sc[4]), MAXNF) : gd[t];
    xs[t] = (sc[5] > MAXNF) ? __fmul_rn(__fdiv_rn(gs[t], sc[5]), MAXNF) : gs[t];
    __syncthreads();
    if (t < 32) {
        float x2 = xla_red_sq(xs, t);
        float y2 = xla_red_sq(xd, t);
        float xy = xla_red_dotneg(xs, xd, t);
        if (t == 0) {
            float t18  = __fmul_rn(1.8f, xy);
            float base = __fadd_rn(1.0f, t18);
            sc[6] = __fadd_rn(base, __fmul_rn(0.9f, y2));
            sc[7] = __fsub_rn(1.0f, __fmul_rn(0.9f, x2));
            float den = __fadd_rn(base, __fmul_rn(__fmul_rn(0.81f, x2), y2));
            sc[8] = fmaxf(den, 1e-15f);
        }
    }
    __syncthreads();
    {
        float xm  = -xs[t];
        float num = __fadd_rn(__fmul_rn(sc[6], xm), __fmul_rn(sc[7], xd[t]));
        dv[t] = __fdiv_rn(num, sc[8]);
    }
    __syncthreads();
    if (t < 32) {
        float n2 = xla_red_sq(dv, t);
        if (t == 0) {
            float nn = __fsqrt_rn(fmaxf(n2, 1e-30f));
            float z  = __fmul_rn(SCF, nn);
            z = fminf(z, CLIPF); z = fmaxf(z, -CLIPF);
            float at = (float)atanh((double)z);
            float pd = __fmul_rn(T2F, at);
            g_sspd[b] = -__fmul_rn(pd, pd);
        }
    }
}

// ------- fused expmap0(norm) + 22 dots + fp32 inverse pdist per word row -----
__global__ __launch_bounds__(256) void rowops() {
    int b = blockIdx.x;
    int l0 = blockIdx.y * 16;
    __shared__ float  se[22*512];
    __shared__ float  sdots[16][22];
    __shared__ float  sf[16];
    __shared__ float  sx2[16];
    __shared__ float  sy2[22];
    int t = threadIdx.x;
    for (int i = t; i < 11264; i += 256) se[i] = g_embs[(long)b*11264 + i];
    if (t < 22) sy2[t] = (float)g_embn2d[b*22 + t];
    __syncthreads();
    int r = t >> 4, cg = t & 15;
    int l = l0 + r;
    int lv = (l < 1019) ? l : 1018;
    const float* u = g_dweraw + ((long)b*1019 + lv)*512;
    float4 ur[8];
#pragma unroll
    for (int i = 0; i < 8; i++) ur[i] = ((const float4*)u)[cg + i*16];
    float s = 0.f;
#pragma unroll
    for (int i = 0; i < 8; i++)
        s += ur[i].x*ur[i].x + ur[i].y*ur[i].y + ur[i].z*ur[i].z + ur[i].w*ur[i].w;
    for (int o = 8; o; o >>= 1) s += __shfl_xor_sync(~0u, s, o);
    {
        float n = sqrtf(fmaxf(s, 1e-30f));
        float scn = SC*n, tt = tanhf(scn);
        float f = tt/scn, gn = tt/SC;
        if (gn > MAXNF) f *= MAXNF/gn;
        if (cg == 0) {
            sf[r] = f;
            float xn = fminf(gn, MAXNF);
            sx2[r] = xn*xn;
        }
    }
    for (int j = 0; j < 22; j++) {
        const float4* e = (const float4*)(se + j*512);
        float d = 0.f;
#pragma unroll
        for (int i = 0; i < 8; i++) {
            float4 ev = e[cg + i*16];
            d += ur[i].x*ev.x + ur[i].y*ev.y + ur[i].z*ev.z + ur[i].w*ev.w;
        }
        for (int o = 8; o; o >>= 1) d += __shfl_xor_sync(~0u, d, o);
        if (cg == 0) sdots[r][j] = d;
    }
    __syncthreads();
    for (int item = t; item < 352; item += 256) {
        int r2 = item/22, j = item - r2*22;
        int l2 = l0 + r2;
        if (l2 < 1019) {
            float xy = sf[r2] * sdots[r2][j];
            float pd = pdist_wf(sx2[r2], sy2[j], xy);
            g_S[((long)b*1024 + l2)*22 + j] = 1.f/pd;
        }
    }
}

// ---------------- final scoring ----------------
__global__ __launch_bounds__(256) void finalk(float* __restrict__ out) {
    int b = blockIdx.x, t = threadIdx.x;
    int w = t >> 5, lane = t & 31;
    __shared__ double sd[22];
    const float4* e0 = (const float4*)(g_embs + (long)b*11264);
    for (int j = w; j < 22; j += 8) {
        const float4* ej = (const float4*)(g_embs + (long)b*11264 + j*512);
        double d = 0.0;
        for (int i = lane; i < 128; i += 32) {
            float4 a = e0[i], c = ej[i];
            d += (double)a.x*c.x + (double)a.y*c.y + (double)a.z*c.z + (double)a.w*c.w;
        }
        for (int o = 16; o; o >>= 1) d += __shfl_xor_sync(~0u, d, o);
        if (lane == 0) sd[j] = d;
    }
    __syncthreads();
    float a_di2 = 0.f, a_si2 = 0.f, a_disi = 0.f;
    float a_c2[20], a_dc[20];
#pragma unroll
    for (int c = 0; c < 20; c++) { a_c2[c] = 0.f; a_dc[c] = 0.f; }
    for (int l = t; l < 1019; l += 256) {
        const float* Srow = g_S + ((long)b*1024 + l)*22;
        float di = Srow[0];
        float si = Srow[1];
        a_di2 += di*di; a_si2 += si*si; a_disi += di*si;
#pragma unroll
        for (int c = 0; c < 20; c++) {
            float ci = Srow[2+c];
            a_c2[c] += ci*ci; a_dc[c] += di*ci;
        }
    }
    __shared__ float rs[43][8];
    float vals[43];
    vals[0] = a_di2; vals[1] = a_si2; vals[2] = a_disi;
#pragma unroll
    for (int c = 0; c < 20; c++) { vals[3+c] = a_c2[c]; vals[23+c] = a_dc[c]; }
#pragma unroll
    for (int k = 0; k < 43; k++) {
        float v = vals[k];
        for (int o = 16; o; o >>= 1) v += __shfl_xor_sync(~0u, v, o);
        if (lane == 0) rs[k][w] = v;
    }
    __syncthreads();
    if (t < 43) {
        float v = 0.f;
        for (int i = 0; i < 8; i++) v += rs[t][i];
        rs[t][0] = v;
    }
    __syncthreads();
    double dn2 = g_embn2d[b*22 + 0];
    float nd = fmaxf(sqrtf(rs[0][0]), 1e-8f);
    if (t == 0) {
        float ns = fmaxf(sqrtf(rs[1][0]), 1e-8f);
        out[80 + b] = __fadd_rn(g_sspd[b], rs[2][0]/(nd*ns));
    }
    if (t < 20) {
        double cn2 = g_embn2d[b*22 + 2 + t];
        double pd = pdist_d(cn2, dn2, sd[2 + t]);
        float nc = fmaxf(sqrtf(rs[3 + t][0]), 1e-8f);
        out[b*20 + t] = (float)(-pd*pd) + rs[23 + t][0]/(nd*nc);
    }
}

// ---------------- launch ----------------
extern "C" void kernel_launch(void* const* d_in, const int* in_sizes, int n_in,
                              void* d_out, int out_size) {
    const float* text = (const float*)d_in[0];
    const float* summ = (const float*)d_in[1];
    const float* cand = (const float*)d_in[2];
    const float* W_d  = (const float*)d_in[3];
    const float* W_s  = (const float*)d_in[4];
    const float* W_c  = (const float*)d_in[5];
    const float* W_p  = (const float*)d_in[6];
    const float* cw1  = (const float*)d_in[7];
    const float* cb1  = (const float*)d_in[8];
    const float* cw2  = (const float*)d_in[9];
    const float* cb2  = (const float*)d_in[10];
    float* out = (float*)d_out;

    void *p_gram, *p_dwe;
    cudaGetSymbolAddress(&p_gram, g_gram);
    cudaGetSymbolAddress(&p_dwe,  g_dweraw);

    static cudaStream_t s2 = nullptr;
    static cudaEvent_t evF = nullptr, evJ = nullptr;
    if (s2 == nullptr) {
        cudaStreamCreateWithFlags(&s2, cudaStreamNonBlocking);
        cudaEventCreateWithFlags(&evF, cudaEventDisableTiming);
        cudaEventCreateWithFlags(&evJ, cudaEventDisableTiming);
    }

    cudaEventRecord(evF, 0);
    cudaStreamWaitEvent(s2, evF, 0);

    // side chain: fused max+GEMM+expmap0 for 88 embeddings, then out1 emulation
    rowgemm<<<88, 128, 0, s2>>>(text, summ, cand, W_d, W_s, W_c);
    emu_rest<<<4, 512, 0, s2>>>();
    cudaEventRecord(evJ, s2);

    // main chain: bf16 GEMMs (y2+y1, then W_p)
    TP3 ta;
    ta.g[0] = { text, cw2, cb2, (float*)p_gram,
                2036, 1536, 509, 512L*768, 768, 768, 1019, 510, 1 };
    ta.g[1] = { text, cw1, cb1, (float*)p_gram,
                2040, 768,  510, 512L*768, 768, 768, 1019, 0,   1 };
    ta.g[2] = ta.g[1];
    ta.end[0] = 128; ta.end[1] = 256; ta.end[2] = 256;
    gemmH<<<256, 256>>>(ta);

    TP3 tw;
    tw.g[0] = { (float*)p_gram, W_p, nullptr, (float*)p_dwe,
                4076, 512, 1019, 1019L*512, 512, 0, 1019, 0, 0 };
    tw.g[1] = tw.g[0]; tw.g[2] = tw.g[0];
    tw.end[0] = 256; tw.end[1] = 256; tw.end[2] = 256;
    gemmH<<<256, 256>>>(tw);

    cudaStreamWaitEvent(0, evJ, 0);

    rowops<<<dim3(4,64), 256>>>();
    finalk<<<4, 256>>>(out);
}

// round 16
// speedup vs baseline: 1.8873x; 1.0900x over previous
#include <cuda_runtime.h>
#include <cuda_bf16.h>
#include <math.h>
#include <stdint.h>

#define SC   0.94868329805051381f
#define SCD  0.94868329805051380976
#define MAXND (0.996/0.94868329805051380976)

#define SCF   ((float)0.94868329805051380976)
#define MAXNF ((float)(0.996/0.94868329805051380976))
#define CLIPF ((float)(1.0 - 1e-7))
#define T2F   ((float)(2.0/0.94868329805051380976))

// ---------------- scratch ----------------
__device__ float  g_embs[4*22*512];
__device__ double g_embn2d[4*22];
__device__ float  g_gram[4*1019*512];
__device__ float  g_dweraw[4*1019*512];
__device__ float  g_S[4*1024*22];
__device__ float  g_sspd[4];
__device__ float  g_emud[4*512];
__device__ float  g_emus[4*512];

// ---------------- pdist helpers ----------------
__device__ __forceinline__ double pdist_z(double x2, double y2, double xy) {
    double A   = 1.0 - 1.8*xy + 0.9*y2;
    double B   = 1.0 - 0.9*x2;
    double den = 1.0 - 1.8*xy + 0.81*x2*y2;
    den = fmax(den, 1e-15);
    double num2 = A*A*x2 - 2.0*A*B*xy + B*B*y2;
    double nd2  = num2/(den*den);
    double n    = sqrt(fmax(nd2, 1e-30));
    return fmin(SCD*n, 1.0 - 1e-7);
}
__device__ __forceinline__ double pdist_d(double x2, double y2, double xy) {
    return (2.0/SCD)*atanh(pdist_z(x2, y2, xy));
}
__device__ __forceinline__ float pdist_wf(float x2, float y2, float xy) {
    float A   = 1.f - 1.8f*xy + 0.9f*y2;
    float B   = 1.f - 0.9f*x2;
    float den = fmaxf(1.f - 1.8f*xy + 0.81f*x2*y2, 1e-15f);
    float num2 = A*A*x2 - 2.f*A*B*xy + B*B*y2;
    float nd2  = num2/(den*den);
    float n    = sqrtf(fmaxf(nd2, 1e-30f));
    float z    = fminf(SC*n, 1.f - 1e-7f);
    return (2.f/SC)*atanhf(z);
}

// ====== fused: max-reduce + per-row chain GEMM + expmap0 (bit-identical) =====
__global__ __launch_bounds__(128) void rowgemm(
    const float* __restrict__ text, const float* __restrict__ summ,
    const float* __restrict__ cand,
    const float* __restrict__ Wd, const float* __restrict__ Ws,
    const float* __restrict__ Wc)
{
    int r = blockIdx.x, t = threadIdx.x;
    __shared__ float sa[768];
    const float* B; float* C; float* C2 = nullptr; int erow;
    if (r < 80) {
        const float* p = cand + (long)r*128*768;
        for (int h = t; h < 768; h += 128) {
            float m = -3.4e38f;
#pragma unroll 4
            for (int l = 0; l < 128; l++) m = fmaxf(m, p[(long)l*768 + h]);
            sa[h] = m;
        }
        B = Wc;
        erow = (r/20)*22 + 2 + (r%20);
        C = g_embs + (long)erow*512;
    } else if (r < 84) {
        int b = r - 80;
        const float* p = text + (long)b*512*768;
        for (int h = t; h < 768; h += 128) sa[h] = p[h];
        B = Wd; erow = b*22;
        C = g_embs + (long)erow*512; C2 = g_emud + b*512;
    } else {
        int b = r - 84;
        const float* p = summ + (long)b*128*768;
        for (int h = t; h < 768; h += 128) {
            float m = -3.4e38f;
#pragma unroll 4
            for (int l = 0; l < 128; l++) m = fmaxf(m, p[(long)l*768 + h]);
            sa[h] = m;
        }
        B = Ws; erow = b*22 + 1;
        C = g_embs + (long)erow*512; C2 = g_emus + b*512;
    }
    __syncthreads();
    int c = t*4;
    float a0 = 0.f, a1 = 0.f, a2 = 0.f, a3 = 0.f;
    for (int k = 0; k < 768; k++) {
        float4 bv = *(const float4*)(B + (long)k*512 + c);
        float ak = sa[k];
        a0 = __fmaf_rn(ak, bv.x, a0);
        a1 = __fmaf_rn(ak, bv.y, a1);
        a2 = __fmaf_rn(ak, bv.z, a2);
        a3 = __fmaf_rn(ak, bv.w, a3);
    }
    if (C2) { C2[c] = a0; C2[c+1] = a1; C2[c+2] = a2; C2[c+3] = a3; }
    float o0 = a0 + 0.f, o1 = a1 + 0.f, o2 = a2 + 0.f, o3 = a3 + 0.f;
    double s = (double)o0*o0 + (double)o1*o1 + (double)o2*o2 + (double)o3*o3;
    for (int o = 16; o; o >>= 1) s += __shfl_xor_sync(~0u, s, o);
    __shared__ double sw[4];
    if ((t & 31) == 0) sw[t >> 5] = s;
    __syncthreads();
    s = sw[0] + sw[1] + sw[2] + sw[3];
    double n = sqrt(fmax(s, 1e-30));
    double scn = SCD*n;
    double tt = tanh(scn);
    double f = tt/scn;
    double gn = tt/SCD;
    if (gn > MAXND) f *= MAXND/gn;
    float ff = (float)f;
    C[c]   = o0*ff; C[c+1] = o1*ff; C[c+2] = o2*ff; C[c+3] = o3*ff;
    if (t == 0) { double xn = fmin(gn, MAXND); g_embn2d[erow] = xn*xn; }
}

// ======= bf16 tensor-core GEMM v3: BM=128 BN=64 BK=32, conflict-free ========
struct GP {
    const float* A; const float* B; const float* bias; float* C;
    int M, K, RPB; long IB, IL, IO; int OB, OO, relu;
};
struct TP3 { GP g[3]; int end[3]; };

#define KP2 40   // bf16 row pitch (80 B): fragment LDS + B STS conflict-free
__global__ __launch_bounds__(256) void gemmH(TP3 ps) {
    __shared__ __nv_bfloat16 As[2][128][KP2];
    __shared__ __nv_bfloat16 Bs[2][64][KP2];
    int id = blockIdx.x;
    int pi = 0, base = 0;
#pragma unroll
    for (int q = 0; q < 3; q++) {
        if (id >= ps.end[q]) { pi = q + 1; base = ps.end[q]; }
    }
    GP p = ps.g[pi];
    int bx = id - base;
    int bm = (bx >> 3) * 128, bn = (bx & 7) * 64;
    int t = threadIdx.x;
    int w = t >> 5, lane = t & 31;
    int g = lane >> 2, tig = lane & 3;
    int wm = w & 3, wn = w >> 2;          // 4 m-warps x 2 n-warps

    // A staging: thread -> row t>>1, k-half (t&1)*16 (covers 128 x 32)
    int ar = t >> 1, kh = (t & 1) * 16;
    int gr = bm + ar; if (gr >= p.M) gr = p.M - 1;
    int ab = gr / p.RPB, al = gr - ab * p.RPB;
    const float* Ap = p.A + ab * p.IB + (long)al * p.IL + p.IO + kh;
    // B staging: thread -> col n=t&63, k-octet (t>>6)*8 (covers 32 x 64)
    int bn6 = t & 63, ko = (t >> 6) * 8;
    const float* Bq = p.B + (long)ko * 512 + bn + bn6;

    float acc[2][4][4];
#pragma unroll
    for (int i = 0; i < 2; i++)
#pragma unroll
        for (int j = 0; j < 4; j++)
#pragma unroll
            for (int r = 0; r < 4; r++) acc[i][j][r] = 0.f;

    int ntiles = p.K >> 5;
    float4 pa0 = *(const float4*)(Ap);
    float4 pa1 = *(const float4*)(Ap + 4);
    float4 pa2 = *(const float4*)(Ap + 8);
    float4 pa3 = *(const float4*)(Ap + 12);
    float pb[8];
#pragma unroll
    for (int i = 0; i < 8; i++) pb[i] = Bq[(long)i * 512];
    {
        __nv_bfloat162 c0 = __floats2bfloat162_rn(pa0.x, pa0.y);
        __nv_bfloat162 c1 = __floats2bfloat162_rn(pa0.z, pa0.w);
        __nv_bfloat162 c2 = __floats2bfloat162_rn(pa1.x, pa1.y);
        __nv_bfloat162 c3 = __floats2bfloat162_rn(pa1.z, pa1.w);
        uint4 k0 = { *(uint32_t*)&c0, *(uint32_t*)&c1, *(uint32_t*)&c2, *(uint32_t*)&c3 };
        c0 = __floats2bfloat162_rn(pa2.x, pa2.y);
        c1 = __floats2bfloat162_rn(pa2.z, pa2.w);
        c2 = __floats2bfloat162_rn(pa3.x, pa3.y);
        c3 = __floats2bfloat162_rn(pa3.z, pa3.w);
        uint4 k1 = { *(uint32_t*)&c0, *(uint32_t*)&c1, *(uint32_t*)&c2, *(uint32_t*)&c3 };
        *(uint4*)&As[0][ar][kh]     = k0;
        *(uint4*)&As[0][ar][kh + 8] = k1;
        __nv_bfloat162 b0 = __floats2bfloat162_rn(pb[0], pb[1]);
        __nv_bfloat162 b1 = __floats2bfloat162_rn(pb[2], pb[3]);
        __nv_bfloat162 b2 = __floats2bfloat162_rn(pb[4], pb[5]);
        __nv_bfloat162 b3 = __floats2bfloat162_rn(pb[6], pb[7]);
        uint4 bk = { *(uint32_t*)&b0, *(uint32_t*)&b1, *(uint32_t*)&b2, *(uint32_t*)&b3 };
        *(uint4*)&Bs[0][bn6][ko] = bk;
    }
    __syncthreads();

    for (int tile = 0; tile < ntiles; tile++) {
        int buf = tile & 1;
        if (tile + 1 < ntiles) {
            long koo = (long)(tile + 1) * 32;
            pa0 = *(const float4*)(Ap + koo);
            pa1 = *(const float4*)(Ap + koo + 4);
            pa2 = *(const float4*)(Ap + koo + 8);
            pa3 = *(const float4*)(Ap + koo + 12);
#pragma unroll
            for (int i = 0; i < 8; i++) pb[i] = Bq[(koo + i) * 512];
        }
#pragma unroll
        for (int ks = 0; ks < 32; ks += 16) {
            uint32_t af[2][4];
#pragma unroll
            for (int mt = 0; mt < 2; mt++) {
                int r = wm*32 + mt*16 + g;
                af[mt][0] = *(const uint32_t*)&As[buf][r    ][ks + 2*tig];
                af[mt][1] = *(const uint32_t*)&As[buf][r + 8][ks + 2*tig];
                af[mt][2] = *(const uint32_t*)&As[buf][r    ][ks + 2*tig + 8];
                af[mt][3] = *(const uint32_t*)&As[buf][r + 8][ks + 2*tig + 8];
            }
            uint32_t bfr[4][2];
#pragma unroll
            for (int nt = 0; nt < 4; nt++) {
                int n = wn*32 + nt*8 + g;
                bfr[nt][0] = *(const uint32_t*)&Bs[buf][n][ks + 2*tig];
                bfr[nt][1] = *(const uint32_t*)&Bs[buf][n][ks + 2*tig + 8];
            }
#pragma unroll
            for (int mt = 0; mt < 2; mt++)
#pragma unroll
                for (int nt = 0; nt < 4; nt++) {
                    asm volatile(
                        "mma.sync.aligned.m16n8k16.row.col.f32.bf16.bf16.f32 "
                        "{%0,%1,%2,%3}, {%4,%5,%6,%7}, {%8,%9}, {%0,%1,%2,%3};"
                        : "+f"(acc[mt][nt][0]), "+f"(acc[mt][nt][1]),
                          "+f"(acc[mt][nt][2]), "+f"(acc[mt][nt][3])
                        : "r"(af[mt][0]), "r"(af[mt][1]), "r"(af[mt][2]), "r"(af[mt][3]),
                          "r"(bfr[nt][0]), "r"(bfr[nt][1]));
                }
        }
        if (tile + 1 < ntiles) {
            int nb = buf ^ 1;
            __nv_bfloat162 c0 = __floats2bfloat162_rn(pa0.x, pa0.y);
            __nv_bfloat162 c1 = __floats2bfloat162_rn(pa0.z, pa0.w);
            __nv_bfloat162 c2 = __floats2bfloat162_rn(pa1.x, pa1.y);
            __nv_bfloat162 c3 = __floats2bfloat162_rn(pa1.z, pa1.w);
            uint4 k0 = { *(uint32_t*)&c0, *(uint32_t*)&c1, *(uint32_t*)&c2, *(uint32_t*)&c3 };
            c0 = __floats2bfloat162_rn(pa2.x, pa2.y);
            c1 = __floats2bfloat162_rn(pa2.z, pa2.w);
            c2 = __floats2bfloat162_rn(pa3.x, pa3.y);
            c3 = __floats2bfloat162_rn(pa3.z, pa3.w);
            uint4 k1 = { *(uint32_t*)&c0, *(uint32_t*)&c1, *(uint32_t*)&c2, *(uint32_t*)&c3 };
            *(uint4*)&As[nb][ar][kh]     = k0;
            *(uint4*)&As[nb][ar][kh + 8] = k1;
            __nv_bfloat162 b0 = __floats2bfloat162_rn(pb[0], pb[1]);
            __nv_bfloat162 b1 = __floats2bfloat162_rn(pb[2], pb[3]);
            __nv_bfloat162 b2 = __floats2bfloat162_rn(pb[4], pb[5]);
            __nv_bfloat162 b3 = __floats2bfloat162_rn(pb[6], pb[7]);
            uint4 bk = { *(uint32_t*)&b0, *(uint32_t*)&b1, *(uint32_t*)&b2, *(uint32_t*)&b3 };
            *(uint4*)&Bs[nb][bn6][ko] = bk;
            __syncthreads();
        }
    }

#pragma unroll
    for (int mt = 0; mt < 2; mt++) {
#pragma unroll
        for (int half = 0; half < 2; half++) {
            int gm = bm + wm*32 + mt*16 + g + half*8;
            if (gm < p.M) {
                int ob = gm / p.RPB, ol = gm - ob*p.RPB;
                float* Crow = p.C + ((long)ob*p.OB + p.OO + ol)*512;
#pragma unroll
                for (int nt = 0; nt < 4; nt++) {
                    int col = bn + wn*32 + nt*8 + 2*tig;
                    float b0 = p.bias ? p.bias[col]   : 0.f;
                    float b1 = p.bias ? p.bias[col+1] : 0.f;
                    float v0 = acc[mt][nt][half*2+0] + b0;
                    float v1 = acc[mt][nt][half*2+1] + b1;
                    if (p.relu) { v0 = fmaxf(v0, 0.f); v1 = fmaxf(v1, 0.f); }
                    Crow[col]   = v0;
                    Crow[col+1] = v1;
                }
            }
        }
    }
}

// =============== bit-replication of the reference summary-doc pdist ==========
__device__ __forceinline__ float xla_red_sq(const float* v, int lane) {
    float a = 0.f;
    for (int m = 0; m < 16; m++) a = __fadd_rn(a, __fmul_rn(v[lane + 32*m], v[lane + 32*m]));
    for (int off = 16; off; off >>= 1) a = __fadd_rn(a, __shfl_down_sync(0xffffffffu, a, off));
    return __shfl_sync(0xffffffffu, a, 0);
}
__device__ __forceinline__ float xla_red_dotneg(const float* v1, const float* v2, int lane) {
    float a = 0.f;
    for (int m = 0; m < 16; m++) {
        int i = lane + 32*m;
        a = __fadd_rn(a, __fmul_rn(-v1[i], v2[i]));
    }
    for (int off = 16; off; off >>= 1) a = __fadd_rn(a, __shfl_down_sync(0xffffffffu, a, off));
    return __shfl_sync(0xffffffffu, a, 0);
}

__global__ __launch_bounds__(512) void emu_rest() {
    int b = blockIdx.x, t = threadIdx.x;
    __shared__ float ud[512], us[512], gd[512], gs[512], xd[512], xs[512], dv[512];
    __shared__ float sc[10];
    ud[t] = g_emud[b*512 + t];
    us[t] = g_emus[b*512 + t];
    __syncthreads();
    if (t < 32) {
        float n2 = xla_red_sq(ud, t);
        float nu = fmaxf(__fsqrt_rn(fmaxf(n2, 1e-30f)), 1e-15f);
        float scn = __fmul_rn(SCF, nu);
        if (t == 0) { sc[0] = scn; sc[2] = (float)tanh((double)scn); }
        n2 = xla_red_sq(us, t);
        nu = fmaxf(__fsqrt_rn(fmaxf(n2, 1e-30f)), 1e-15f);
        scn = __fmul_rn(SCF, nu);
        if (t == 0) { sc[1] = scn; sc[3] = (float)tanh((double)scn); }
    }
    __syncthreads();
    gd[t] = __fdiv_rn(__fmul_rn(sc[2], ud[t]), sc[0]);
    gs[t] = __fdiv_rn(__fmul_rn(sc[3], us[t]), sc[1]);
    __syncthreads();
    if (t < 32) {
        float n2 = xla_red_sq(gd, t);
        float ng = fmaxf(__fsqrt_rn(fmaxf(n2, 1e-30f)), 1e-15f);
        if (t == 0) sc[4] = ng;
        n2 = xla_red_sq(gs, t);
        ng = fmaxf(__fsqrt_rn(fmaxf(n2, 1e-30f)), 1e-15f);
        if (t == 0) sc[5] = ng;
    }
    __syncthreads();
    xd[t] = (sc[4] > MAXNF) ? __fmul_rn(__fdiv_rn(gd[t], sc[4]), MAXNF) : gd[t];
    xs[t] = (sc[5] > MAXNF) ? __fmul_rn(__fdiv_rn(gs[t], sc[5]), MAXNF) : gs[t];
    __syncthreads();
    if (t < 32) {
        float x2 = xla_red_sq(xs, t);
        float y2 = xla_red_sq(xd, t);
        float xy = xla_red_dotneg(xs, xd, t);
        if (t == 0) {
            float t18  = __fmul_rn(1.8f, xy);
            float base = __fadd_rn(1.0f, t18);
            sc[6] = __fadd_rn(base, __fmul_rn(0.9f, y2));
            sc[7] = __fsub_rn(1.0f, __fmul_rn(0.9f, x2));
            float den = __fadd_rn(base, __fmul_rn(__fmul_rn(0.81f, x2), y2));
            sc[8] = fmaxf(den, 1e-15f);
        }
    }
    __syncthreads();
    {
        float xm  = -xs[t];
        float num = __fadd_rn(__fmul_rn(sc[6], xm), __fmul_rn(sc[7], xd[t]));
        dv[t] = __fdiv_rn(num, sc[8]);
    }
    __syncthreads();
    if (t < 32) {
        float n2 = xla_red_sq(dv, t);
        if (t == 0) {
            float nn = __fsqrt_rn(fmaxf(n2, 1e-30f));
            float z  = __fmul_rn(SCF, nn);
            z = fminf(z, CLIPF); z = fmaxf(z, -CLIPF);
            float at = (float)atanh((double)z);
            float pd = __fmul_rn(T2F, at);
            g_sspd[b] = -__fmul_rn(pd, pd);
        }
    }
}

// ------- fused expmap0(norm) + 22 dots + fp32 inverse pdist per word row -----
__global__ __launch_bounds__(256) void rowops() {
    int b = blockIdx.x;
    int l0 = blockIdx.y * 16;
    __shared__ float  se[22*512];
    __shared__ float  sdots[16][22];
    __shared__ float  sf[16];
    __shared__ float  sx2[16];
    __shared__ float  sy2[22];
    int t = threadIdx.x;
    for (int i = t; i < 11264; i += 256) se[i] = g_embs[(long)b*11264 + i];
    if (t < 22) sy2[t] = (float)g_embn2d[b*22 + t];
    __syncthreads();
    int r = t >> 4, cg = t & 15;
    int l = l0 + r;
    int lv = (l < 1019) ? l : 1018;
    const float* u = g_dweraw + ((long)b*1019 + lv)*512;
    float4 ur[8];
#pragma unroll
    for (int i = 0; i < 8; i++) ur[i] = ((const float4*)u)[cg + i*16];
    float s = 0.f;
#pragma unroll
    for (int i = 0; i < 8; i++)
        s += ur[i].x*ur[i].x + ur[i].y*ur[i].y + ur[i].z*ur[i].z + ur[i].w*ur[i].w;
    for (int o = 8; o; o >>= 1) s += __shfl_xor_sync(~0u, s, o);
    {
        float n = sqrtf(fmaxf(s, 1e-30f));
        float scn = SC*n, tt = tanhf(scn);
        float f = tt/scn, gn = tt/SC;
        if (gn > MAXNF) f *= MAXNF/gn;
        if (cg == 0) {
            sf[r] = f;
            float xn = fminf(gn, MAXNF);
            sx2[r] = xn*xn;
        }
    }
    for (int j = 0; j < 22; j++) {
        const float4* e = (const float4*)(se + j*512);
        float d = 0.f;
#pragma unroll
        for (int i = 0; i < 8; i++) {
            float4 ev = e[cg + i*16];
            d += ur[i].x*ev.x + ur[i].y*ev.y + ur[i].z*ev.z + ur[i].w*ev.w;
        }
        for (int o = 8; o; o >>= 1) d += __shfl_xor_sync(~0u, d, o);
        if (cg == 0) sdots[r][j] = d;
    }
    __syncthreads();
    for (int item = t; item < 352; item += 256) {
        int r2 = item/22, j = item - r2*22;
        int l2 = l0 + r2;
        if (l2 < 1019) {
            float xy = sf[r2] * sdots[r2][j];
            float pd = pdist_wf(sx2[r2], sy2[j], xy);
            g_S[((long)b*1024 + l2)*22 + j] = 1.f/pd;
        }
    }
}

// ---------------- final scoring ----------------
__global__ __launch_bounds__(256) void finalk(float* __restrict__ out) {
    int b = blockIdx.x, t = threadIdx.x;
    int w = t >> 5, lane = t & 31;
    __shared__ double sd[22];
    const float4* e0 = (const float4*)(g_embs + (long)b*11264);
    for (int j = w; j < 22; j += 8) {
        const float4* ej = (const float4*)(g_embs + (long)b*11264 + j*512);
        double d = 0.0;
        for (int i = lane; i < 128; i += 32) {
            float4 a = e0[i], c = ej[i];
            d += (double)a.x*c.x + (double)a.y*c.y + (double)a.z*c.z + (double)a.w*c.w;
        }
        for (int o = 16; o; o >>= 1) d += __shfl_xor_sync(~0u, d, o);
        if (lane == 0) sd[j] = d;
    }
    __syncthreads();
    float a_di2 = 0.f, a_si2 = 0.f, a_disi = 0.f;
    float a_c2[20], a_dc[20];
#pragma unroll
    for (int c = 0; c < 20; c++) { a_c2[c] = 0.f; a_dc[c] = 0.f; }
    for (int l = t; l < 1019; l += 256) {
        const float* Srow = g_S + ((long)b*1024 + l)*22;
        float di = Srow[0];
        float si = Srow[1];
        a_di2 += di*di; a_si2 += si*si; a_disi += di*si;
#pragma unroll
        for (int c = 0; c < 20; c++) {
            float ci = Srow[2+c];
            a_c2[c] += ci*ci; a_dc[c] += di*ci;
        }
    }
    __shared__ float rs[43][8];
    float vals[43];
    vals[0] = a_di2; vals[1] = a_si2; vals[2] = a_disi;
#pragma unroll
    for (int c = 0; c < 20; c++) { vals[3+c] = a_c2[c]; vals[23+c] = a_dc[c]; }
#pragma unroll
    for (int k = 0; k < 43; k++) {
        float v = vals[k];
        for (int o = 16; o; o >>= 1) v += __shfl_xor_sync(~0u, v, o);
        if (lane == 0) rs[k][w] = v;
    }
    __syncthreads();
    if (t < 43) {
        float v = 0.f;
        for (int i = 0; i < 8; i++) v += rs[t][i];
        rs[t][0] = v;
    }
    __syncthreads();
    double dn2 = g_embn2d[b*22 + 0];
    float nd = fmaxf(sqrtf(rs[0][0]), 1e-8f);
    if (t == 0) {
        float ns = fmaxf(sqrtf(rs[1][0]), 1e-8f);
        out[80 + b] = __fadd_rn(g_sspd[b], rs[2][0]/(nd*ns));
    }
    if (t < 20) {
        double cn2 = g_embn2d[b*22 + 2 + t];
        double pd = pdist_d(cn2, dn2, sd[2 + t]);
        float nc = fmaxf(sqrtf(rs[3 + t][0]), 1e-8f);
        out[b*20 + t] = (float)(-pd*pd) + rs[23 + t][0]/(nd*nc);
    }
}

// ---------------- launch ----------------
extern "C" void kernel_launch(void* const* d_in, const int* in_sizes, int n_in,
                              void* d_out, int out_size) {
    const float* text = (const float*)d_in[0];
    const float* summ = (const float*)d_in[1];
    const float* cand = (const float*)d_in[2];
    const float* W_d  = (const float*)d_in[3];
    const float* W_s  = (const float*)d_in[4];
    const float* W_c  = (const float*)d_in[5];
    const float* W_p  = (const float*)d_in[6];
    const float* cw1  = (const float*)d_in[7];
    const float* cb1  = (const float*)d_in[8];
    const float* cw2  = (const float*)d_in[9];
    const float* cb2  = (const float*)d_in[10];
    float* out = (float*)d_out;

    void *p_gram, *p_dwe;
    cudaGetSymbolAddress(&p_gram, g_gram);
    cudaGetSymbolAddress(&p_dwe,  g_dweraw);

    static cudaStream_t s2 = nullptr;
    static cudaEvent_t evF = nullptr, evJ = nullptr;
    if (s2 == nullptr) {
        cudaStreamCreateWithFlags(&s2, cudaStreamNonBlocking);
        cudaEventCreateWithFlags(&evF, cudaEventDisableTiming);
        cudaEventCreateWithFlags(&evJ, cudaEventDisableTiming);
    }

    cudaEventRecord(evF, 0);
    cudaStreamWaitEvent(s2, evF, 0);

    // side chain: fused max+GEMM+expmap0 for 88 embeddings, then out1 emulation
    rowgemm<<<88, 128, 0, s2>>>(text, summ, cand, W_d, W_s, W_c);
    emu_rest<<<4, 512, 0, s2>>>();
    cudaEventRecord(evJ, s2);

    // main chain: bf16 GEMMs (y2+y1, then W_p), BK=32
    TP3 ta;
    ta.g[0] = { text, cw2, cb2, (float*)p_gram,
                2036, 1536, 509, 512L*768, 768, 768, 1019, 510, 1 };
    ta.g[1] = { text, cw1, cb1, (float*)p_gram,
                2040, 768,  510, 512L*768, 768, 768, 1019, 0,   1 };
    ta.g[2] = ta.g[1];
    ta.end[0] = 128; ta.end[1] = 256; ta.end[2] = 256;
    gemmH<<<256, 256>>>(ta);

    TP3 tw;
    tw.g[0] = { (float*)p_gram, W_p, nullptr, (float*)p_dwe,
                4076, 512, 1019, 1019L*512, 512, 0, 1019, 0, 0 };
    tw.g[1] = tw.g[0]; tw.g[2] = tw.g[0];
    tw.end[0] = 256; tw.end[1] = 256; tw.end[2] = 256;
    gemmH<<<256, 256>>>(tw);

    cudaStreamWaitEvent(0, evJ, 0);

    rowops<<<dim3(4,64), 256>>>();
    finalk<<<4, 256>>>(out);
}

// round 17
// speedup vs baseline: 2.0242x; 1.0725x over previous
#include <cuda_runtime.h>
#include <cuda_bf16.h>
#include <math.h>
#include <stdint.h>

#define SC   0.94868329805051381f
#define SCD  0.94868329805051380976
#define MAXND (0.996/0.94868329805051380976)

#define SCF   ((float)0.94868329805051380976)
#define MAXNF ((float)(0.996/0.94868329805051380976))
#define CLIPF ((float)(1.0 - 1e-7))
#define T2F   ((float)(2.0/0.94868329805051380976))

// ---------------- scratch ----------------
__device__ float  g_smax[4*768];
__device__ float  g_cmax[4*20*768];
__device__ float  g_embs[4*22*512];
__device__ double g_embn2d[4*22];
__device__ float  g_gram[4*1019*512];
__device__ float  g_dweraw[4*1019*512];
__device__ float  g_S[4*1024*22];
__device__ float  g_sspd[4];
__device__ float  g_emud[4*512];
__device__ float  g_emus[4*512];

// ---------------- pdist helpers ----------------
__device__ __forceinline__ double pdist_z(double x2, double y2, double xy) {
    double A   = 1.0 - 1.8*xy + 0.9*y2;
    double B   = 1.0 - 0.9*x2;
    double den = 1.0 - 1.8*xy + 0.81*x2*y2;
    den = fmax(den, 1e-15);
    double num2 = A*A*x2 - 2.0*A*B*xy + B*B*y2;
    double nd2  = num2/(den*den);
    double n    = sqrt(fmax(nd2, 1e-30));
    return fmin(SCD*n, 1.0 - 1e-7);
}
__device__ __forceinline__ double pdist_d(double x2, double y2, double xy) {
    return (2.0/SCD)*atanh(pdist_z(x2, y2, xy));
}
__device__ __forceinline__ float pdist_wf(float x2, float y2, float xy) {
    float A   = 1.f - 1.8f*xy + 0.9f*y2;
    float B   = 1.f - 0.9f*x2;
    float den = fmaxf(1.f - 1.8f*xy + 0.81f*x2*y2, 1e-15f);
    float num2 = A*A*x2 - 2.f*A*B*xy + B*B*y2;
    float nd2  = num2/(den*den);
    float n    = sqrtf(fmaxf(nd2, 1e-30f));
    float z    = fminf(SC*n, 1.f - 1e-7f);
    return (2.f/SC)*atanhf(z);
}

// ---------------- max over sequence dims (full-chip, MLP-8) ----------------
__global__ void maxk(const float* __restrict__ sum_out,
                     const float* __restrict__ cand_out) {
    int idx = blockIdx.x*blockDim.x + threadIdx.x;
    if (idx < 3072) {
        int b = idx/768, h = idx - b*768;
        const float* p = sum_out + (long)b*128*768 + h;
        float m = -3.4e38f;
#pragma unroll 8
        for (int l = 0; l < 128; l++) m = fmaxf(m, p[(long)l*768]);
        g_smax[idx] = m;
    } else {
        int i = idx - 3072;
        if (i < 61440) {
            int bc = i/768, h = i - bc*768;
            const float* p = cand_out + (long)bc*128*768 + h;
            float m = -3.4e38f;
#pragma unroll 8
            for (int l = 0; l < 128; l++) m = fmaxf(m, p[(long)l*768]);
            g_cmax[i] = m;
        }
    }
}

// ====== small GEMMs per-row chains + fused expmap0 (bit-identical) ==========
__global__ __launch_bounds__(128) void rowgemm(
    const float* __restrict__ text,
    const float* __restrict__ Wd, const float* __restrict__ Ws,
    const float* __restrict__ Wc)
{
    int r = blockIdx.x, t = threadIdx.x;
    __shared__ float sa[768];
    const float* B; float* C; float* C2 = nullptr; int erow;
    if (r < 80) {
        for (int h = t; h < 768; h += 128) sa[h] = g_cmax[r*768 + h];
        B = Wc;
        erow = (r/20)*22 + 2 + (r%20);
        C = g_embs + (long)erow*512;
    } else if (r < 84) {
        int b = r - 80;
        const float* p = text + (long)b*512*768;
        for (int h = t; h < 768; h += 128) sa[h] = p[h];
        B = Wd; erow = b*22;
        C = g_embs + (long)erow*512; C2 = g_emud + b*512;
    } else {
        int b = r - 84;
        for (int h = t; h < 768; h += 128) sa[h] = g_smax[b*768 + h];
        B = Ws; erow = b*22 + 1;
        C = g_embs + (long)erow*512; C2 = g_emus + b*512;
    }
    __syncthreads();
    int c = t*4;
    float a0 = 0.f, a1 = 0.f, a2 = 0.f, a3 = 0.f;
    for (int k = 0; k < 768; k++) {
        float4 bv = *(const float4*)(B + (long)k*512 + c);
        float ak = sa[k];
        a0 = __fmaf_rn(ak, bv.x, a0);
        a1 = __fmaf_rn(ak, bv.y, a1);
        a2 = __fmaf_rn(ak, bv.z, a2);
        a3 = __fmaf_rn(ak, bv.w, a3);
    }
    if (C2) { C2[c] = a0; C2[c+1] = a1; C2[c+2] = a2; C2[c+3] = a3; }
    float o0 = a0 + 0.f, o1 = a1 + 0.f, o2 = a2 + 0.f, o3 = a3 + 0.f;
    double s = (double)o0*o0 + (double)o1*o1 + (double)o2*o2 + (double)o3*o3;
    for (int o = 16; o; o >>= 1) s += __shfl_xor_sync(~0u, s, o);
    __shared__ double sw[4];
    if ((t & 31) == 0) sw[t >> 5] = s;
    __syncthreads();
    s = sw[0] + sw[1] + sw[2] + sw[3];
    double n = sqrt(fmax(s, 1e-30));
    double scn = SCD*n;
    double tt = tanh(scn);
    double f = tt/scn;
    double gn = tt/SCD;
    if (gn > MAXND) f *= MAXND/gn;
    float ff = (float)f;
    C[c]   = o0*ff; C[c+1] = o1*ff; C[c+2] = o2*ff; C[c+3] = o3*ff;
    if (t == 0) { double xn = fmin(gn, MAXND); g_embn2d[erow] = xn*xn; }
}

// ======= bf16 tensor-core GEMM v3: BM=128 BN=64 BK=32, conflict-free ========
struct GP {
    const float* A; const float* B; const float* bias; float* C;
    int M, K, RPB; long IB, IL, IO; int OB, OO, relu;
};
struct TP3 { GP g[3]; int end[3]; };

#define KP2 40   // bf16 row pitch (80 B): fragment LDS + B STS conflict-free
__global__ __launch_bounds__(256) void gemmH(TP3 ps) {
    __shared__ __nv_bfloat16 As[2][128][KP2];
    __shared__ __nv_bfloat16 Bs[2][64][KP2];
    int id = blockIdx.x;
    int pi = 0, base = 0;
#pragma unroll
    for (int q = 0; q < 3; q++) {
        if (id >= ps.end[q]) { pi = q + 1; base = ps.end[q]; }
    }
    GP p = ps.g[pi];
    int bx = id - base;
    int bm = (bx >> 3) * 128, bn = (bx & 7) * 64;
    int t = threadIdx.x;
    int w = t >> 5, lane = t & 31;
    int g = lane >> 2, tig = lane & 3;
    int wm = w & 3, wn = w >> 2;

    int ar = t >> 1, kh = (t & 1) * 16;
    int gr = bm + ar; if (gr >= p.M) gr = p.M - 1;
    int ab = gr / p.RPB, al = gr - ab * p.RPB;
    const float* Ap = p.A + ab * p.IB + (long)al * p.IL + p.IO + kh;
    int bn6 = t & 63, ko = (t >> 6) * 8;
    const float* Bq = p.B + (long)ko * 512 + bn + bn6;

    float acc[2][4][4];
#pragma unroll
    for (int i = 0; i < 2; i++)
#pragma unroll
        for (int j = 0; j < 4; j++)
#pragma unroll
            for (int r = 0; r < 4; r++) acc[i][j][r] = 0.f;

    int ntiles = p.K >> 5;
    float4 pa0 = *(const float4*)(Ap);
    float4 pa1 = *(const float4*)(Ap + 4);
    float4 pa2 = *(const float4*)(Ap + 8);
    float4 pa3 = *(const float4*)(Ap + 12);
    float pb[8];
#pragma unroll
    for (int i = 0; i < 8; i++) pb[i] = Bq[(long)i * 512];
    {
        __nv_bfloat162 c0 = __floats2bfloat162_rn(pa0.x, pa0.y);
        __nv_bfloat162 c1 = __floats2bfloat162_rn(pa0.z, pa0.w);
        __nv_bfloat162 c2 = __floats2bfloat162_rn(pa1.x, pa1.y);
        __nv_bfloat162 c3 = __floats2bfloat162_rn(pa1.z, pa1.w);
        uint4 k0 = { *(uint32_t*)&c0, *(uint32_t*)&c1, *(uint32_t*)&c2, *(uint32_t*)&c3 };
        c0 = __floats2bfloat162_rn(pa2.x, pa2.y);
        c1 = __floats2bfloat162_rn(pa2.z, pa2.w);
        c2 = __floats2bfloat162_rn(pa3.x, pa3.y);
        c3 = __floats2bfloat162_rn(pa3.z, pa3.w);
        uint4 k1 = { *(uint32_t*)&c0, *(uint32_t*)&c1, *(uint32_t*)&c2, *(uint32_t*)&c3 };
        *(uint4*)&As[0][ar][kh]     = k0;
        *(uint4*)&As[0][ar][kh + 8] = k1;
        __nv_bfloat162 b0 = __floats2bfloat162_rn(pb[0], pb[1]);
        __nv_bfloat162 b1 = __floats2bfloat162_rn(pb[2], pb[3]);
        __nv_bfloat162 b2 = __floats2bfloat162_rn(pb[4], pb[5]);
        __nv_bfloat162 b3 = __floats2bfloat162_rn(pb[6], pb[7]);
        uint4 bk = { *(uint32_t*)&b0, *(uint32_t*)&b1, *(uint32_t*)&b2, *(uint32_t*)&b3 };
        *(uint4*)&Bs[0][bn6][ko] = bk;
    }
    __syncthreads();

    for (int tile = 0; tile < ntiles; tile++) {
        int buf = tile & 1;
        if (tile + 1 < ntiles) {
            long koo = (long)(tile + 1) * 32;
            pa0 = *(const float4*)(Ap + koo);
            pa1 = *(const float4*)(Ap + koo + 4);
            pa2 = *(const float4*)(Ap + koo + 8);
            pa3 = *(const float4*)(Ap + koo + 12);
#pragma unroll
            for (int i = 0; i < 8; i++) pb[i] = Bq[(koo + i) * 512];
        }
#pragma unroll
        for (int ks = 0; ks < 32; ks += 16) {
            uint32_t af[2][4];
#pragma unroll
            for (int mt = 0; mt < 2; mt++) {
                int r = wm*32 + mt*16 + g;
                af[mt][0] = *(const uint32_t*)&As[buf][r    ][ks + 2*tig];
                af[mt][1] = *(const uint32_t*)&As[buf][r + 8][ks + 2*tig];
                af[mt][2] = *(const uint32_t*)&As[buf][r    ][ks + 2*tig + 8];
                af[mt][3] = *(const uint32_t*)&As[buf][r + 8][ks + 2*tig + 8];
            }
            uint32_t bfr[4][2];
#pragma unroll
            for (int nt = 0; nt < 4; nt++) {
                int n = wn*32 + nt*8 + g;
                bfr[nt][0] = *(const uint32_t*)&Bs[buf][n][ks + 2*tig];
                bfr[nt][1] = *(const uint32_t*)&Bs[buf][n][ks + 2*tig + 8];
            }
#pragma unroll
            for (int mt = 0; mt < 2; mt++)
#pragma unroll
                for (int nt = 0; nt < 4; nt++) {
                    asm volatile(
                        "mma.sync.aligned.m16n8k16.row.col.f32.bf16.bf16.f32 "
                        "{%0,%1,%2,%3}, {%4,%5,%6,%7}, {%8,%9}, {%0,%1,%2,%3};"
                        : "+f"(acc[mt][nt][0]), "+f"(acc[mt][nt][1]),
                          "+f"(acc[mt][nt][2]), "+f"(acc[mt][nt][3])
                        : "r"(af[mt][0]), "r"(af[mt][1]), "r"(af[mt][2]), "r"(af[mt][3]),
                          "r"(bfr[nt][0]), "r"(bfr[nt][1]));
                }
        }
        if (tile + 1 < ntiles) {
            int nb = buf ^ 1;
            __nv_bfloat162 c0 = __floats2bfloat162_rn(pa0.x, pa0.y);
            __nv_bfloat162 c1 = __floats2bfloat162_rn(pa0.z, pa0.w);
            __nv_bfloat162 c2 = __floats2bfloat162_rn(pa1.x, pa1.y);
            __nv_bfloat162 c3 = __floats2bfloat162_rn(pa1.z, pa1.w);
            uint4 k0 = { *(uint32_t*)&c0, *(uint32_t*)&c1, *(uint32_t*)&c2, *(uint32_t*)&c3 };
            c0 = __floats2bfloat162_rn(pa2.x, pa2.y);
            c1 = __floats2bfloat162_rn(pa2.z, pa2.w);
            c2 = __floats2bfloat162_rn(pa3.x, pa3.y);
            c3 = __floats2bfloat162_rn(pa3.z, pa3.w);
            uint4 k1 = { *(uint32_t*)&c0, *(uint32_t*)&c1, *(uint32_t*)&c2, *(uint32_t*)&c3 };
            *(uint4*)&As[nb][ar][kh]     = k0;
            *(uint4*)&As[nb][ar][kh + 8] = k1;
            __nv_bfloat162 b0 = __floats2bfloat162_rn(pb[0], pb[1]);
            __nv_bfloat162 b1 = __floats2bfloat162_rn(pb[2], pb[3]);
            __nv_bfloat162 b2 = __floats2bfloat162_rn(pb[4], pb[5]);
            __nv_bfloat162 b3 = __floats2bfloat162_rn(pb[6], pb[7]);
            uint4 bk = { *(uint32_t*)&b0, *(uint32_t*)&b1, *(uint32_t*)&b2, *(uint32_t*)&b3 };
            *(uint4*)&Bs[nb][bn6][ko] = bk;
            __syncthreads();
        }
    }

#pragma unroll
    for (int mt = 0; mt < 2; mt++) {
#pragma unroll
        for (int half = 0; half < 2; half++) {
            int gm = bm + wm*32 + mt*16 + g + half*8;
            if (gm < p.M) {
                int ob = gm / p.RPB, ol = gm - ob*p.RPB;
                float* Crow = p.C + ((long)ob*p.OB + p.OO + ol)*512;
#pragma unroll
                for (int nt = 0; nt < 4; nt++) {
                    int col = bn + wn*32 + nt*8 + 2*tig;
                    float b0 = p.bias ? p.bias[col]   : 0.f;
                    float b1 = p.bias ? p.bias[col+1] : 0.f;
                    float v0 = acc[mt][nt][half*2+0] + b0;
                    float v1 = acc[mt][nt][half*2+1] + b1;
                    if (p.relu) { v0 = fmaxf(v0, 0.f); v1 = fmaxf(v1, 0.f); }
                    Crow[col]   = v0;
                    Crow[col+1] = v1;
                }
            }
        }
    }
}

// =============== bit-replication of the reference summary-doc pdist ==========
__device__ __forceinline__ float xla_red_sq(const float* v, int lane) {
    float a = 0.f;
    for (int m = 0; m < 16; m++) a = __fadd_rn(a, __fmul_rn(v[lane + 32*m], v[lane + 32*m]));
    for (int off = 16; off; off >>= 1) a = __fadd_rn(a, __shfl_down_sync(0xffffffffu, a, off));
    return __shfl_sync(0xffffffffu, a, 0);
}
__device__ __forceinline__ float xla_red_dotneg(const float* v1, const float* v2, int lane) {
    float a = 0.f;
    for (int m = 0; m < 16; m++) {
        int i = lane + 32*m;
        a = __fadd_rn(a, __fmul_rn(-v1[i], v2[i]));
    }
    for (int off = 16; off; off >>= 1) a = __fadd_rn(a, __shfl_down_sync(0xffffffffu, a, off));
    return __shfl_sync(0xffffffffu, a, 0);
}

__global__ __launch_bounds__(512) void emu_rest() {
    int b = blockIdx.x, t = threadIdx.x;
    __shared__ float ud[512], us[512], gd[512], gs[512], xd[512], xs[512], dv[512];
    __shared__ float sc[10];
    ud[t] = g_emud[b*512 + t];
    us[t] = g_emus[b*512 + t];
    __syncthreads();
    if (t < 32) {
        float n2 = xla_red_sq(ud, t);
        float nu = fmaxf(__fsqrt_rn(fmaxf(n2, 1e-30f)), 1e-15f);
        float scn = __fmul_rn(SCF, nu);
        if (t == 0) { sc[0] = scn; sc[2] = (float)tanh((double)scn); }
        n2 = xla_red_sq(us, t);
        nu = fmaxf(__fsqrt_rn(fmaxf(n2, 1e-30f)), 1e-15f);
        scn = __fmul_rn(SCF, nu);
        if (t == 0) { sc[1] = scn; sc[3] = (float)tanh((double)scn); }
    }
    __syncthreads();
    gd[t] = __fdiv_rn(__fmul_rn(sc[2], ud[t]), sc[0]);
    gs[t] = __fdiv_rn(__fmul_rn(sc[3], us[t]), sc[1]);
    __syncthreads();
    if (t < 32) {
        float n2 = xla_red_sq(gd, t);
        float ng = fmaxf(__fsqrt_rn(fmaxf(n2, 1e-30f)), 1e-15f);
        if (t == 0) sc[4] = ng;
        n2 = xla_red_sq(gs, t);
        ng = fmaxf(__fsqrt_rn(fmaxf(n2, 1e-30f)), 1e-15f);
        if (t == 0) sc[5] = ng;
    }
    __syncthreads();
    xd[t] = (sc[4] > MAXNF) ? __fmul_rn(__fdiv_rn(gd[t], sc[4]), MAXNF) : gd[t];
    xs[t] = (sc[5] > MAXNF) ? __fmul_rn(__fdiv_rn(gs[t], sc[5]), MAXNF) : gs[t];
    __syncthreads();
    if (t < 32) {
        float x2 = xla_red_sq(xs, t);
        float y2 = xla_red_sq(xd, t);
        float xy = xla_red_dotneg(xs, xd, t);
        if (t == 0) {
            float t18  = __fmul_rn(1.8f, xy);
            float base = __fadd_rn(1.0f, t18);
            sc[6] = __fadd_rn(base, __fmul_rn(0.9f, y2));
            sc[7] = __fsub_rn(1.0f, __fmul_rn(0.9f, x2));
            float den = __fadd_rn(base, __fmul_rn(__fmul_rn(0.81f, x2), y2));
            sc[8] = fmaxf(den, 1e-15f);
        }
    }
    __syncthreads();
    {
        float xm  = -xs[t];
        float num = __fadd_rn(__fmul_rn(sc[6], xm), __fmul_rn(sc[7], xd[t]));
        dv[t] = __fdiv_rn(num, sc[8]);
    }
    __syncthreads();
    if (t < 32) {
        float n2 = xla_red_sq(dv, t);
        if (t == 0) {
            float nn = __fsqrt_rn(fmaxf(n2, 1e-30f));
            float z  = __fmul_rn(SCF, nn);
            z = fminf(z, CLIPF); z = fmaxf(z, -CLIPF);
            float at = (float)atanh((double)z);
            float pd = __fmul_rn(T2F, at);
            g_sspd[b] = -__fmul_rn(pd, pd);
        }
    }
}

// ------- fused expmap0(norm) + 22 dots + fp32 inverse pdist per word row -----
__global__ __launch_bounds__(256) void rowops() {
    int b = blockIdx.x;
    int l0 = blockIdx.y * 16;
    __shared__ float  se[22*512];
    __shared__ float  sdots[16][22];
    __shared__ float  sf[16];
    __shared__ float  sx2[16];
    __shared__ float  sy2[22];
    int t = threadIdx.x;
    for (int i = t; i < 11264; i += 256) se[i] = g_embs[(long)b*11264 + i];
    if (t < 22) sy2[t] = (float)g_embn2d[b*22 + t];
    __syncthreads();
    int r = t >> 4, cg = t & 15;
    int l = l0 + r;
    int lv = (l < 1019) ? l : 1018;
    const float* u = g_dweraw + ((long)b*1019 + lv)*512;
    float4 ur[8];
#pragma unroll
    for (int i = 0; i < 8; i++) ur[i] = ((const float4*)u)[cg + i*16];
    float s = 0.f;
#pragma unroll
    for (int i = 0; i < 8; i++)
        s += ur[i].x*ur[i].x + ur[i].y*ur[i].y + ur[i].z*ur[i].z + ur[i].w*ur[i].w;
    for (int o = 8; o; o >>= 1) s += __shfl_xor_sync(~0u, s, o);
    {
        float n = sqrtf(fmaxf(s, 1e-30f));
        float scn = SC*n, tt = tanhf(scn);
        float f = tt/scn, gn = tt/SC;
        if (gn > MAXNF) f *= MAXNF/gn;
        if (cg == 0) {
            sf[r] = f;
            float xn = fminf(gn, MAXNF);
            sx2[r] = xn*xn;
        }
    }
    for (int j = 0; j < 22; j++) {
        const float4* e = (const float4*)(se + j*512);
        float d = 0.f;
#pragma unroll
        for (int i = 0; i < 8; i++) {
            float4 ev = e[cg + i*16];
            d += ur[i].x*ev.x + ur[i].y*ev.y + ur[i].z*ev.z + ur[i].w*ev.w;
        }
        for (int o = 8; o; o >>= 1) d += __shfl_xor_sync(~0u, d, o);
        if (cg == 0) sdots[r][j] = d;
    }
    __syncthreads();
    for (int item = t; item < 352; item += 256) {
        int r2 = item/22, j = item - r2*22;
        int l2 = l0 + r2;
        if (l2 < 1019) {
            float xy = sf[r2] * sdots[r2][j];
            float pd = pdist_wf(sx2[r2], sy2[j], xy);
            g_S[((long)b*1024 + l2)*22 + j] = 1.f/pd;
        }
    }
}

// ---------------- final scoring ----------------
__global__ __launch_bounds__(256) void finalk(float* __restrict__ out) {
    int b = blockIdx.x, t = threadIdx.x;
    int w = t >> 5, lane = t & 31;
    __shared__ double sd[22];
    const float4* e0 = (const float4*)(g_embs + (long)b*11264);
    for (int j = w; j < 22; j += 8) {
        const float4* ej = (const float4*)(g_embs + (long)b*11264 + j*512);
        double d = 0.0;
        for (int i = lane; i < 128; i += 32) {
            float4 a = e0[i], c = ej[i];
            d += (double)a.x*c.x + (double)a.y*c.y + (double)a.z*c.z + (double)a.w*c.w;
        }
        for (int o = 16; o; o >>= 1) d += __shfl_xor_sync(~0u, d, o);
        if (lane == 0) sd[j] = d;
    }
    __syncthreads();
    float a_di2 = 0.f, a_si2 = 0.f, a_disi = 0.f;
    float a_c2[20], a_dc[20];
#pragma unroll
    for (int c = 0; c < 20; c++) { a_c2[c] = 0.f; a_dc[c] = 0.f; }
    for (int l = t; l < 1019; l += 256) {
        const float* Srow = g_S + ((long)b*1024 + l)*22;
        float di = Srow[0];
        float si = Srow[1];
        a_di2 += di*di; a_si2 += si*si; a_disi += di*si;
#pragma unroll
        for (int c = 0; c < 20; c++) {
            float ci = Srow[2+c];
            a_c2[c] += ci*ci; a_dc[c] += di*ci;
        }
    }
    __shared__ float rs[43][8];
    float vals[43];
    vals[0] = a_di2; vals[1] = a_si2; vals[2] = a_disi;
#pragma unroll
    for (int c = 0; c < 20; c++) { vals[3+c] = a_c2[c]; vals[23+c] = a_dc[c]; }
#pragma unroll
    for (int k = 0; k < 43; k++) {
        float v = vals[k];
        for (int o = 16; o; o >>= 1) v += __shfl_xor_sync(~0u, v, o);
        if (lane == 0) rs[k][w] = v;
    }
    __syncthreads();
    if (t < 43) {
        float v = 0.f;
        for (int i = 0; i < 8; i++) v += rs[t][i];
        rs[t][0] = v;
    }
    __syncthreads();
    double dn2 = g_embn2d[b*22 + 0];
    float nd = fmaxf(sqrtf(rs[0][0]), 1e-8f);
    if (t == 0) {
        float ns = fmaxf(sqrtf(rs[1][0]), 1e-8f);
        out[80 + b] = __fadd_rn(g_sspd[b], rs[2][0]/(nd*ns));
    }
    if (t < 20) {
        double cn2 = g_embn2d[b*22 + 2 + t];
        double pd = pdist_d(cn2, dn2, sd[2 + t]);
        float nc = fmaxf(sqrtf(rs[3 + t][0]), 1e-8f);
        out[b*20 + t] = (float)(-pd*pd) + rs[23 + t][0]/(nd*nc);
    }
}

// ---------------- launch ----------------
extern "C" void kernel_launch(void* const* d_in, const int* in_sizes, int n_in,
                              void* d_out, int out_size) {
    const float* text = (const float*)d_in[0];
    const float* summ = (const float*)d_in[1];
    const float* cand = (const float*)d_in[2];
    const float* W_d  = (const float*)d_in[3];
    const float* W_s  = (const float*)d_in[4];
    const float* W_c  = (const float*)d_in[5];
    const float* W_p  = (const float*)d_in[6];
    const float* cw1  = (const float*)d_in[7];
    const float* cb1  = (const float*)d_in[8];
    const float* cw2  = (const float*)d_in[9];
    const float* cb2  = (const float*)d_in[10];
    float* out = (float*)d_out;

    void *p_gram, *p_dwe;
    cudaGetSymbolAddress(&p_gram, g_gram);
    cudaGetSymbolAddress(&p_dwe,  g_dweraw);

    static cudaStream_t s2 = nullptr;
    static cudaEvent_t evF = nullptr, evJ = nullptr;
    if (s2 == nullptr) {
        cudaStreamCreateWithFlags(&s2, cudaStreamNonBlocking);
        cudaEventCreateWithFlags(&evF, cudaEventDisableTiming);
        cudaEventCreateWithFlags(&evJ, cudaEventDisableTiming);
    }

    cudaEventRecord(evF, 0);
    cudaStreamWaitEvent(s2, evF, 0);

    // side chain: full-chip max-reduce, then small GEMMs+expmap0, then out1 emu
    maxk<<<252, 256, 0, s2>>>(summ, cand);
    rowgemm<<<88, 128, 0, s2>>>(text, W_d, W_s, W_c);
    emu_rest<<<4, 512, 0, s2>>>();
    cudaEventRecord(evJ, s2);

    // main chain: bf16 GEMMs (y2+y1, then W_p), BK=32
    TP3 ta;
    ta.g[0] = { text, cw2, cb2, (float*)p_gram,
                2036, 1536, 509, 512L*768, 768, 768, 1019, 510, 1 };
    ta.g[1] = { text, cw1, cb1, (float*)p_gram,
                2040, 768,  510, 512L*768, 768, 768, 1019, 0,   1 };
    ta.g[2] = ta.g[1];
    ta.end[0] = 128; ta.end[1] = 256; ta.end[2] = 256;
    gemmH<<<256, 256>>>(ta);

    TP3 tw;
    tw.g[0] = { (float*)p_gram, W_p, nullptr, (float*)p_dwe,
                4076, 512, 1019, 1019L*512, 512, 0, 1019, 0, 0 };
    tw.g[1] = tw.g[0]; tw.g[2] = tw.g[0];
    tw.end[0] = 256; tw.end[1] = 256; tw.end[2] = 256;
    gemmH<<<256, 256>>>(tw);

    cudaStreamWaitEvent(0, evJ, 0);

    rowops<<<dim3(4,64), 256>>>();
    finalk<<<4, 256>>>(out);
}